// round 8
// baseline (speedup 1.0000x reference)
#include <cuda_runtime.h>
#include <cuda_fp16.h>
#include <math.h>

// Problem constants
#define BB 4
#define NN 2048
#define CC 384
#define HH 8
#define HD 48
#define TT (BB * NN)          // 8192 tokens
#define SCALE 0.14433756729740645f  // 1/sqrt(48)

// Scratch (static device globals — no runtime allocation)
__device__ float g_Q[TT * CC];
__device__ float g_K[TT * CC];
__device__ float g_V[TT * CC];
__device__ float g_X[TT * CC];
__device__ __half g_Qh[TT * CC];   // head-major: [B][H][N][HD]
__device__ __half g_Kh[TT * CC];
__device__ __half g_Vh[TT * CC];

// ---------------------------------------------------------------------------
// MMA / async-copy helpers
// ---------------------------------------------------------------------------
__device__ __forceinline__ void ldsm_x4(unsigned int addr, unsigned int& r0,
                                        unsigned int& r1, unsigned int& r2, unsigned int& r3)
{
    asm volatile("ldmatrix.sync.aligned.m8n8.x4.shared.b16 {%0,%1,%2,%3}, [%4];"
                 : "=r"(r0), "=r"(r1), "=r"(r2), "=r"(r3) : "r"(addr));
}
__device__ __forceinline__ void ldsm_x4_t(unsigned int addr, unsigned int& r0,
                                          unsigned int& r1, unsigned int& r2, unsigned int& r3)
{
    asm volatile("ldmatrix.sync.aligned.m8n8.x4.trans.shared.b16 {%0,%1,%2,%3}, [%4];"
                 : "=r"(r0), "=r"(r1), "=r"(r2), "=r"(r3) : "r"(addr));
}
__device__ __forceinline__ void mma16816(float* c, unsigned int a0, unsigned int a1,
                                         unsigned int a2, unsigned int a3,
                                         unsigned int b0, unsigned int b1)
{
    asm volatile("mma.sync.aligned.m16n8k16.row.col.f32.f16.f16.f32 "
                 "{%0,%1,%2,%3}, {%4,%5,%6,%7}, {%8,%9}, {%0,%1,%2,%3};"
                 : "+f"(c[0]), "+f"(c[1]), "+f"(c[2]), "+f"(c[3])
                 : "r"(a0), "r"(a1), "r"(a2), "r"(a3), "r"(b0), "r"(b1));
}
__device__ __forceinline__ unsigned int packh2(float x, float y)
{
    __half2 h = __floats2half2_rn(x, y);
    return *reinterpret_cast<unsigned int*>(&h);
}
__device__ __forceinline__ void cp16(unsigned int saddr, const void* gptr)
{
    asm volatile("cp.async.cg.shared.global [%0], [%1], 16;" :: "r"(saddr), "l"(gptr));
}
#define CP_COMMIT() asm volatile("cp.async.commit_group;")
#define CP_WAIT(n)  asm volatile("cp.async.wait_group %0;" :: "n"(n))

// ---------------------------------------------------------------------------
// Split-fp16 tensor-core GEMM with FUSED fp32->(hi,lo) conversion.
// out[m][n] = sum_k A[m][k]*W[n][k] + bias[n]; A, W fp32 in global.
// Computes hi*hi + lo*hi + hi*lo with fp32 accumulators (~22-bit mantissa).
// CTA tile 128x64, BK=32, 8 warps (4 m-warps x 2 n-warps, 32x32 per warp).
// ---------------------------------------------------------------------------
#define GS 40   // shared row stride in halfs (80B: conflict-free ldmatrix)

__global__ __launch_bounds__(256) void gemm_h3f(const float* __restrict__ A,
                                                const float* __restrict__ W,
                                                const float* __restrict__ bias,
                                                float* __restrict__ out)
{
    __shared__ __half sAh[128 * GS];
    __shared__ __half sAl[128 * GS];
    __shared__ __half sWh[64 * GS];
    __shared__ __half sWl[64 * GS];

    int tid = threadIdx.x, lane = tid & 31, warp = tid >> 5;
    int wm = warp & 3, wn = warp >> 2;
    int row0 = blockIdx.y * 128;
    int col0 = blockIdx.x * 64;

    float acc[2][4][4];
#pragma unroll
    for (int mt = 0; mt < 2; mt++)
#pragma unroll
        for (int n8 = 0; n8 < 4; n8++)
#pragma unroll
            for (int j = 0; j < 4; j++) acc[mt][n8][j] = 0.f;

    unsigned int ah_b = (unsigned int)__cvta_generic_to_shared(sAh);
    unsigned int al_b = (unsigned int)__cvta_generic_to_shared(sAl);
    unsigned int wh_b = (unsigned int)__cvta_generic_to_shared(sWh);
    unsigned int wl_b = (unsigned int)__cvta_generic_to_shared(sWl);

    int a_off = (wm * 32 + (lane & 15)) * GS + (lane >> 4) * 8;
    int w_off = (wn * 32 + (lane & 7) + ((lane >> 4) & 1) * 8) * GS + ((lane >> 3) & 1) * 8;

    for (int k0 = 0; k0 < CC; k0 += 32) {
        __syncthreads();
        // Stage A (128x32 fp32 -> hi/lo planes): 1024 float4, 4 per thread
#pragma unroll
        for (int p = 0; p < 4; p++) {
            int e = tid + p * 256;
            int r = e >> 3, c4 = (e & 7) * 4;
            float4 x = *(const float4*)(A + (size_t)(row0 + r) * CC + k0 + c4);
            __half2 h01 = __floats2half2_rn(x.x, x.y);
            __half2 h23 = __floats2half2_rn(x.z, x.w);
            float2 f01 = __half22float2(h01);
            float2 f23 = __half22float2(h23);
            __half2 l01 = __floats2half2_rn(x.x - f01.x, x.y - f01.y);
            __half2 l23 = __floats2half2_rn(x.z - f23.x, x.w - f23.y);
            uint2 ho, lo;
            ho.x = *reinterpret_cast<unsigned int*>(&h01);
            ho.y = *reinterpret_cast<unsigned int*>(&h23);
            lo.x = *reinterpret_cast<unsigned int*>(&l01);
            lo.y = *reinterpret_cast<unsigned int*>(&l23);
            *(uint2*)&sAh[r * GS + c4] = ho;
            *(uint2*)&sAl[r * GS + c4] = lo;
        }
        // Stage W (64x32 fp32 -> hi/lo planes): 512 float4, 2 per thread
#pragma unroll
        for (int p = 0; p < 2; p++) {
            int e = tid + p * 256;
            int r = e >> 3, c4 = (e & 7) * 4;
            float4 x = *(const float4*)(W + (size_t)(col0 + r) * CC + k0 + c4);
            __half2 h01 = __floats2half2_rn(x.x, x.y);
            __half2 h23 = __floats2half2_rn(x.z, x.w);
            float2 f01 = __half22float2(h01);
            float2 f23 = __half22float2(h23);
            __half2 l01 = __floats2half2_rn(x.x - f01.x, x.y - f01.y);
            __half2 l23 = __floats2half2_rn(x.z - f23.x, x.w - f23.y);
            uint2 ho, lo;
            ho.x = *reinterpret_cast<unsigned int*>(&h01);
            ho.y = *reinterpret_cast<unsigned int*>(&h23);
            lo.x = *reinterpret_cast<unsigned int*>(&l01);
            lo.y = *reinterpret_cast<unsigned int*>(&l23);
            *(uint2*)&sWh[r * GS + c4] = ho;
            *(uint2*)&sWl[r * GS + c4] = lo;
        }
        __syncthreads();

#pragma unroll
        for (int kt = 0; kt < 2; kt++) {
            unsigned int ah[2][4], al[2][4];
#pragma unroll
            for (int mt = 0; mt < 2; mt++) {
                unsigned int off = (unsigned int)((a_off + mt * 16 * GS + kt * 16) * 2);
                ldsm_x4(ah_b + off, ah[mt][0], ah[mt][1], ah[mt][2], ah[mt][3]);
                ldsm_x4(al_b + off, al[mt][0], al[mt][1], al[mt][2], al[mt][3]);
            }
#pragma unroll
            for (int nt = 0; nt < 2; nt++) {
                unsigned int off = (unsigned int)((w_off + nt * 16 * GS + kt * 16) * 2);
                unsigned int wh0, wh1, wh2, wh3, wl0, wl1, wl2, wl3;
                ldsm_x4(wh_b + off, wh0, wh1, wh2, wh3);
                ldsm_x4(wl_b + off, wl0, wl1, wl2, wl3);
#pragma unroll
                for (int mt = 0; mt < 2; mt++) {
                    float* c0 = acc[mt][nt * 2 + 0];
                    float* c1 = acc[mt][nt * 2 + 1];
                    mma16816(c0, ah[mt][0], ah[mt][1], ah[mt][2], ah[mt][3], wh0, wh1);
                    mma16816(c1, ah[mt][0], ah[mt][1], ah[mt][2], ah[mt][3], wh2, wh3);
                    mma16816(c0, al[mt][0], al[mt][1], al[mt][2], al[mt][3], wh0, wh1);
                    mma16816(c1, al[mt][0], al[mt][1], al[mt][2], al[mt][3], wh2, wh3);
                    mma16816(c0, ah[mt][0], ah[mt][1], ah[mt][2], ah[mt][3], wl0, wl1);
                    mma16816(c1, ah[mt][0], ah[mt][1], ah[mt][2], ah[mt][3], wl2, wl3);
                }
            }
        }
    }

#pragma unroll
    for (int mt = 0; mt < 2; mt++) {
        int r = row0 + wm * 32 + mt * 16 + (lane >> 2);
#pragma unroll
        for (int n8 = 0; n8 < 4; n8++) {
            int c = col0 + wn * 32 + n8 * 8 + (lane & 3) * 2;
            float bx = bias[c], by = bias[c + 1];
            float2 f0, f1;
            f0.x = acc[mt][n8][0] + bx; f0.y = acc[mt][n8][1] + by;
            f1.x = acc[mt][n8][2] + bx; f1.y = acc[mt][n8][3] + by;
            *(float2*)&out[(size_t)r * CC + c] = f0;
            *(float2*)&out[(size_t)(r + 8) * CC + c] = f1;
        }
    }
}

// ---------------------------------------------------------------------------
// RoPE3D + fp16 convert + transpose to head-major [B][H][N][HD].
// ---------------------------------------------------------------------------
__global__ void rope_cvt(const float* __restrict__ X, const int* __restrict__ pos,
                         __half* __restrict__ dst, float mult)
{
    int idx = blockIdx.x * blockDim.x + threadIdx.x;
    if (idx >= TT * HH * 3) return;
    int a = idx % 3;
    int h = (idx / 3) % HH;
    int t = idx / (3 * HH);
    int b = t / NN, n = t % NN;

    float p = (float)pos[t * 3 + a];
    const float* x = X + (size_t)t * CC + h * HD + a * 16;

    float v[16];
#pragma unroll
    for (int c = 0; c < 4; c++) {
        float4 f = ((const float4*)x)[c];
        v[c * 4 + 0] = f.x; v[c * 4 + 1] = f.y; v[c * 4 + 2] = f.z; v[c * 4 + 3] = f.w;
    }

    const float LOG2_100 = 6.643856189774724f;
#pragma unroll
    for (int j = 0; j < 8; j++) {
        float inv = exp2f(-(float)j * 0.125f * LOG2_100);
        float ang = p * inv;
        float sn, cs;
        sincosf(ang, &sn, &cs);
        float x1 = v[j], x2 = v[j + 8];
        v[j]     = x1 * cs - x2 * sn;
        v[j + 8] = x2 * cs + x1 * sn;
    }

    unsigned int r[8];
#pragma unroll
    for (int i = 0; i < 8; i++) {
        __half2 h2 = __floats2half2_rn(v[2 * i] * mult, v[2 * i + 1] * mult);
        r[i] = *reinterpret_cast<unsigned int*>(&h2);
    }
    __half* d = dst + ((size_t)(b * HH + h) * NN + n) * HD + a * 16;
    uint4 o0 = {r[0], r[1], r[2], r[3]};
    uint4 o1 = {r[4], r[5], r[6], r[7]};
    ((uint4*)d)[0] = o0;
    ((uint4*)d)[1] = o1;
}

// V: fp16 convert + transpose to head-major (no rope).
__global__ void v_cvt(const float* __restrict__ V, __half* __restrict__ dst)
{
    int idx = blockIdx.x * blockDim.x + threadIdx.x;
    if (idx >= TT * HH) return;
    int h = idx % HH;
    int t = idx / HH;
    int b = t / NN, n = t % NN;

    const float* src = V + (size_t)t * CC + h * HD;
    __half* d = dst + ((size_t)(b * HH + h) * NN + n) * HD;
#pragma unroll
    for (int c = 0; c < 6; c++) {
        float4 f0 = ((const float4*)src)[2 * c];
        float4 f1 = ((const float4*)src)[2 * c + 1];
        __half2 h0 = __floats2half2_rn(f0.x, f0.y);
        __half2 h1 = __floats2half2_rn(f0.z, f0.w);
        __half2 h2 = __floats2half2_rn(f1.x, f1.y);
        __half2 h3 = __floats2half2_rn(f1.z, f1.w);
        uint4 o;
        o.x = *reinterpret_cast<unsigned int*>(&h0);
        o.y = *reinterpret_cast<unsigned int*>(&h1);
        o.z = *reinterpret_cast<unsigned int*>(&h2);
        o.w = *reinterpret_cast<unsigned int*>(&h3);
        ((uint4*)d)[c] = o;
    }
}

// ---------------------------------------------------------------------------
// Tensor-core flash attention.
// Block: 128 queries, 8 warps (warp = 16 query rows). Key tiles of 64,
// double-buffered via cp.async to overlap global->shared with compute.
// ---------------------------------------------------------------------------
#define ATS 56   // shared row stride in halfs (112B rows, 16B-aligned)
#define QT 128

__global__ __launch_bounds__(256) void attn_mma(const __half* __restrict__ Qh,
                                                const __half* __restrict__ Kh,
                                                const __half* __restrict__ Vh,
                                                float* __restrict__ X)
{
    __shared__ __half Qs[QT * ATS];
    __shared__ __half Ks[2][64 * ATS];
    __shared__ __half Vs[2][64 * ATS];

    int tid = threadIdx.x, lane = tid & 31, w = tid >> 5;
    int b = blockIdx.z, h = blockIdx.y;
    const size_t hb = ((size_t)(b * HH + h)) * NN * HD;
    int q0 = blockIdx.x * QT;

    unsigned int qs_base = (unsigned int)__cvta_generic_to_shared(Qs);
    unsigned int ks_base = (unsigned int)__cvta_generic_to_shared(&Ks[0][0]);
    unsigned int vs_base = (unsigned int)__cvta_generic_to_shared(&Vs[0][0]);
    const unsigned int BUFB = 64 * ATS * 2;  // buffer stride in bytes

    // Stage Q tile (128 x 48 halfs): 768 uint4, 3 per thread
    for (int e = tid; e < QT * 6; e += 256) {
        int r = e / 6, c = e % 6;
        *(uint4*)&Qs[r * ATS + c * 8] = *(const uint4*)(Qh + hb + (size_t)(q0 + r) * HD + c * 8);
    }

    // Prefetch K/V tile 0 into buffer 0
    for (int e = tid; e < 384; e += 256) {
        int r = e / 6, c = e % 6;
        size_t g = hb + (size_t)r * HD + c * 8;
        unsigned int so = (unsigned int)((r * ATS + c * 8) * 2);
        cp16(ks_base + so, Kh + g);
        cp16(vs_base + so, Vh + g);
    }
    CP_COMMIT();
    __syncthreads();

    // Q A-fragments (persist across all key tiles)
    unsigned int qa[3][4];
    {
        int arow = w * 16 + (lane & 15);
        int acol = (lane >> 4) * 8;
#pragma unroll
        for (int k = 0; k < 3; k++) {
            unsigned int addr = qs_base + (unsigned int)((arow * ATS + k * 16 + acol) * 2);
            ldsm_x4(addr, qa[k][0], qa[k][1], qa[k][2], qa[k][3]);
        }
    }

    float o[6][4];
#pragma unroll
    for (int n = 0; n < 6; n++)
#pragma unroll
        for (int j = 0; j < 4; j++) o[n][j] = 0.f;
    float m0 = -1e30f, m1 = -1e30f, l0 = 0.f, l1 = 0.f;

    int kb_off = ((lane & 7) + ((lane >> 4) & 1) * 8) * ATS + ((lane >> 3) & 1) * 8;
    int vb_off = ((lane & 7) + ((lane >> 3) & 1) * 8) * ATS + ((lane >> 4) & 1) * 8;

    const int NT = NN / 64;   // 32 tiles
    for (int kt = 0; kt < NT; kt++) {
        // Prefetch next tile into the other buffer
        if (kt + 1 < NT) {
            unsigned int bo = ((kt + 1) & 1) * BUFB;
            for (int e = tid; e < 384; e += 256) {
                int r = e / 6, c = e % 6;
                size_t g = hb + (size_t)((kt + 1) * 64 + r) * HD + c * 8;
                unsigned int so = (unsigned int)((r * ATS + c * 8) * 2);
                cp16(ks_base + bo + so, Kh + g);
                cp16(vs_base + bo + so, Vh + g);
            }
            CP_COMMIT();
            CP_WAIT(1);
        } else {
            CP_WAIT(0);
        }
        __syncthreads();

        unsigned int bo = (kt & 1) * BUFB;

        // S = Q K^T
        float s[8][4];
#pragma unroll
        for (int n = 0; n < 8; n++)
#pragma unroll
            for (int j = 0; j < 4; j++) s[n][j] = 0.f;

#pragma unroll
        for (int np = 0; np < 4; np++) {
#pragma unroll
            for (int k = 0; k < 3; k++) {
                unsigned int addr = ks_base + bo +
                    (unsigned int)(((np * 16) * ATS + k * 16 + kb_off) * 2);
                unsigned int b0, b1, b2, b3;
                ldsm_x4(addr, b0, b1, b2, b3);
                mma16816(s[2 * np],     qa[k][0], qa[k][1], qa[k][2], qa[k][3], b0, b1);
                mma16816(s[2 * np + 1], qa[k][0], qa[k][1], qa[k][2], qa[k][3], b2, b3);
            }
        }

        // Online softmax
        float tm0 = s[0][0], tm1 = s[0][2];
#pragma unroll
        for (int n = 0; n < 8; n++) {
            tm0 = fmaxf(tm0, fmaxf(s[n][0], s[n][1]));
            tm1 = fmaxf(tm1, fmaxf(s[n][2], s[n][3]));
        }
        tm0 = fmaxf(tm0, __shfl_xor_sync(0xffffffffu, tm0, 1));
        tm0 = fmaxf(tm0, __shfl_xor_sync(0xffffffffu, tm0, 2));
        tm1 = fmaxf(tm1, __shfl_xor_sync(0xffffffffu, tm1, 1));
        tm1 = fmaxf(tm1, __shfl_xor_sync(0xffffffffu, tm1, 2));

        float nm0 = fmaxf(m0, tm0), nm1 = fmaxf(m1, tm1);
        float al0 = __expf(m0 - nm0), al1 = __expf(m1 - nm1);
        m0 = nm0; m1 = nm1;
        l0 *= al0; l1 *= al1;
#pragma unroll
        for (int n = 0; n < 6; n++) {
            o[n][0] *= al0; o[n][1] *= al0;
            o[n][2] *= al1; o[n][3] *= al1;
        }
#pragma unroll
        for (int n = 0; n < 8; n++) {
            s[n][0] = __expf(s[n][0] - m0);
            s[n][1] = __expf(s[n][1] - m0);
            s[n][2] = __expf(s[n][2] - m1);
            s[n][3] = __expf(s[n][3] - m1);
            l0 += s[n][0] + s[n][1];
            l1 += s[n][2] + s[n][3];
        }

        // O += P V
#pragma unroll
        for (int ktile = 0; ktile < 4; ktile++) {
            unsigned int a0 = packh2(s[2 * ktile][0],     s[2 * ktile][1]);
            unsigned int a1 = packh2(s[2 * ktile][2],     s[2 * ktile][3]);
            unsigned int a2 = packh2(s[2 * ktile + 1][0], s[2 * ktile + 1][1]);
            unsigned int a3 = packh2(s[2 * ktile + 1][2], s[2 * ktile + 1][3]);
#pragma unroll
            for (int np = 0; np < 3; np++) {
                unsigned int addr = vs_base + bo +
                    (unsigned int)(((ktile * 16) * ATS + np * 16 + vb_off) * 2);
                unsigned int b0, b1, b2, b3;
                ldsm_x4_t(addr, b0, b1, b2, b3);
                mma16816(o[2 * np],     a0, a1, a2, a3, b0, b1);
                mma16816(o[2 * np + 1], a0, a1, a2, a3, b2, b3);
            }
        }
        __syncthreads();
    }

    l0 += __shfl_xor_sync(0xffffffffu, l0, 1);
    l0 += __shfl_xor_sync(0xffffffffu, l0, 2);
    l1 += __shfl_xor_sync(0xffffffffu, l1, 1);
    l1 += __shfl_xor_sync(0xffffffffu, l1, 2);
    float i0 = 1.f / l0, i1 = 1.f / l1;

    int r0 = q0 + w * 16 + (lane >> 2);
    int cbase = h * HD + (lane & 3) * 2;
#pragma unroll
    for (int n = 0; n < 6; n++) {
        float2 f0; f0.x = o[n][0] * i0; f0.y = o[n][1] * i0;
        float2 f1; f1.x = o[n][2] * i1; f1.y = o[n][3] * i1;
        *(float2*)&X[(size_t)(b * NN + r0) * CC + cbase + n * 8] = f0;
        *(float2*)&X[(size_t)(b * NN + r0 + 8) * CC + cbase + n * 8] = f1;
    }
}

// ---------------------------------------------------------------------------
// Launch
// ---------------------------------------------------------------------------
extern "C" void kernel_launch(void* const* d_in, const int* in_sizes, int n_in,
                              void* d_out, int out_size)
{
    const float* query = (const float*)d_in[0];
    const float* key   = (const float*)d_in[1];
    const float* value = (const float*)d_in[2];
    const float* Wq = (const float*)d_in[3];
    const float* bq = (const float*)d_in[4];
    const float* Wk = (const float*)d_in[5];
    const float* bk = (const float*)d_in[6];
    const float* Wv = (const float*)d_in[7];
    const float* bv = (const float*)d_in[8];
    const float* Wo = (const float*)d_in[9];
    const float* bo = (const float*)d_in[10];
    const int* qpos = (const int*)d_in[11];
    const int* kpos = (const int*)d_in[12];
    float* out = (float*)d_out;

    float *pQ, *pK, *pV, *pX;
    __half *pQh, *pKh, *pVh;
    cudaGetSymbolAddress((void**)&pQ, g_Q);
    cudaGetSymbolAddress((void**)&pK, g_K);
    cudaGetSymbolAddress((void**)&pV, g_V);
    cudaGetSymbolAddress((void**)&pX, g_X);
    cudaGetSymbolAddress((void**)&pQh, g_Qh);
    cudaGetSymbolAddress((void**)&pKh, g_Kh);
    cudaGetSymbolAddress((void**)&pVh, g_Vh);

    dim3 ggrid(CC / 64, TT / 128);   // (6, 64)

    gemm_h3f<<<ggrid, 256>>>(query, Wq, bq, pQ);
    gemm_h3f<<<ggrid, 256>>>(key,   Wk, bk, pK);
    gemm_h3f<<<ggrid, 256>>>(value, Wv, bv, pV);

    int rope_threads = TT * HH * 3;
    rope_cvt<<<(rope_threads + 255) / 256, 256>>>(pQ, qpos, pQh, SCALE);
    rope_cvt<<<(rope_threads + 255) / 256, 256>>>(pK, kpos, pKh, 1.0f);
    v_cvt<<<(TT * HH + 255) / 256, 256>>>(pV, pVh);

    attn_mma<<<dim3(NN / QT, HH, BB), 256>>>(pQh, pKh, pVh, pX);

    gemm_h3f<<<ggrid, 256>>>(pX, Wo, bo, out);
}

// round 9
// speedup vs baseline: 1.0545x; 1.0545x over previous
#include <cuda_runtime.h>
#include <cuda_fp16.h>
#include <math.h>

// Problem constants
#define BB 4
#define NN 2048
#define CC 384
#define HH 8
#define HD 48
#define TT (BB * NN)          // 8192 tokens
#define SCALE 0.14433756729740645f       // 1/sqrt(48)
#define QMULT 0.20823444283700469f       // SCALE * log2(e)

// Scratch (static device globals — no runtime allocation)
__device__ float g_Q[TT * CC];
__device__ float g_K[TT * CC];
__device__ float g_V[TT * CC];
__device__ float g_X[TT * CC];
__device__ __half g_Qh[TT * CC];   // head-major: [B][H][N][HD]
__device__ __half g_Kh[TT * CC];
__device__ __half g_Vh[TT * CC];

// ---------------------------------------------------------------------------
// MMA / async-copy helpers
// ---------------------------------------------------------------------------
__device__ __forceinline__ void ldsm_x4(unsigned int addr, unsigned int& r0,
                                        unsigned int& r1, unsigned int& r2, unsigned int& r3)
{
    asm volatile("ldmatrix.sync.aligned.m8n8.x4.shared.b16 {%0,%1,%2,%3}, [%4];"
                 : "=r"(r0), "=r"(r1), "=r"(r2), "=r"(r3) : "r"(addr));
}
__device__ __forceinline__ void ldsm_x4_t(unsigned int addr, unsigned int& r0,
                                          unsigned int& r1, unsigned int& r2, unsigned int& r3)
{
    asm volatile("ldmatrix.sync.aligned.m8n8.x4.trans.shared.b16 {%0,%1,%2,%3}, [%4];"
                 : "=r"(r0), "=r"(r1), "=r"(r2), "=r"(r3) : "r"(addr));
}
__device__ __forceinline__ void mma16816(float* c, unsigned int a0, unsigned int a1,
                                         unsigned int a2, unsigned int a3,
                                         unsigned int b0, unsigned int b1)
{
    asm volatile("mma.sync.aligned.m16n8k16.row.col.f32.f16.f16.f32 "
                 "{%0,%1,%2,%3}, {%4,%5,%6,%7}, {%8,%9}, {%0,%1,%2,%3};"
                 : "+f"(c[0]), "+f"(c[1]), "+f"(c[2]), "+f"(c[3])
                 : "r"(a0), "r"(a1), "r"(a2), "r"(a3), "r"(b0), "r"(b1));
}
__device__ __forceinline__ unsigned int packh2(float x, float y)
{
    __half2 h = __floats2half2_rn(x, y);
    return *reinterpret_cast<unsigned int*>(&h);
}
__device__ __forceinline__ float ex2f(float x)
{
    float r; asm("ex2.approx.ftz.f32 %0, %1;" : "=f"(r) : "f"(x)); return r;
}
__device__ __forceinline__ void cp16(unsigned int saddr, const void* gptr)
{
    asm volatile("cp.async.cg.shared.global [%0], [%1], 16;" :: "r"(saddr), "l"(gptr));
}
#define CP_COMMIT() asm volatile("cp.async.commit_group;")
#define CP_WAIT(n)  asm volatile("cp.async.wait_group %0;" :: "n"(n))

// ---------------------------------------------------------------------------
// Split-fp16 tensor-core GEMM with FUSED fp32->(hi,lo) conversion.
// out[m][n] = sum_k A[m][k]*W[n][k] + bias[n]; A, W fp32 in global.
// hi*hi + lo*hi + hi*lo with fp32 accumulators (~22-bit mantissa).
// CTA tile 128x64, BK=32, 8 warps (4 m-warps x 2 n-warps, 32x32 per warp).
// ---------------------------------------------------------------------------
#define GS 40   // shared row stride in halfs (80B: conflict-free ldmatrix)

__global__ __launch_bounds__(256) void gemm_h3f(const float* __restrict__ A,
                                                const float* __restrict__ W,
                                                const float* __restrict__ bias,
                                                float* __restrict__ out)
{
    __shared__ __half sAh[128 * GS];
    __shared__ __half sAl[128 * GS];
    __shared__ __half sWh[64 * GS];
    __shared__ __half sWl[64 * GS];

    int tid = threadIdx.x, lane = tid & 31, warp = tid >> 5;
    int wm = warp & 3, wn = warp >> 2;
    int row0 = blockIdx.y * 128;
    int col0 = blockIdx.x * 64;

    float acc[2][4][4];
#pragma unroll
    for (int mt = 0; mt < 2; mt++)
#pragma unroll
        for (int n8 = 0; n8 < 4; n8++)
#pragma unroll
            for (int j = 0; j < 4; j++) acc[mt][n8][j] = 0.f;

    unsigned int ah_b = (unsigned int)__cvta_generic_to_shared(sAh);
    unsigned int al_b = (unsigned int)__cvta_generic_to_shared(sAl);
    unsigned int wh_b = (unsigned int)__cvta_generic_to_shared(sWh);
    unsigned int wl_b = (unsigned int)__cvta_generic_to_shared(sWl);

    int a_off = (wm * 32 + (lane & 15)) * GS + (lane >> 4) * 8;
    int w_off = (wn * 32 + (lane & 7) + ((lane >> 4) & 1) * 8) * GS + ((lane >> 3) & 1) * 8;

    for (int k0 = 0; k0 < CC; k0 += 32) {
        __syncthreads();
#pragma unroll
        for (int p = 0; p < 4; p++) {
            int e = tid + p * 256;
            int r = e >> 3, c4 = (e & 7) * 4;
            float4 x = *(const float4*)(A + (size_t)(row0 + r) * CC + k0 + c4);
            __half2 h01 = __floats2half2_rn(x.x, x.y);
            __half2 h23 = __floats2half2_rn(x.z, x.w);
            float2 f01 = __half22float2(h01);
            float2 f23 = __half22float2(h23);
            __half2 l01 = __floats2half2_rn(x.x - f01.x, x.y - f01.y);
            __half2 l23 = __floats2half2_rn(x.z - f23.x, x.w - f23.y);
            uint2 ho, lo;
            ho.x = *reinterpret_cast<unsigned int*>(&h01);
            ho.y = *reinterpret_cast<unsigned int*>(&h23);
            lo.x = *reinterpret_cast<unsigned int*>(&l01);
            lo.y = *reinterpret_cast<unsigned int*>(&l23);
            *(uint2*)&sAh[r * GS + c4] = ho;
            *(uint2*)&sAl[r * GS + c4] = lo;
        }
#pragma unroll
        for (int p = 0; p < 2; p++) {
            int e = tid + p * 256;
            int r = e >> 3, c4 = (e & 7) * 4;
            float4 x = *(const float4*)(W + (size_t)(col0 + r) * CC + k0 + c4);
            __half2 h01 = __floats2half2_rn(x.x, x.y);
            __half2 h23 = __floats2half2_rn(x.z, x.w);
            float2 f01 = __half22float2(h01);
            float2 f23 = __half22float2(h23);
            __half2 l01 = __floats2half2_rn(x.x - f01.x, x.y - f01.y);
            __half2 l23 = __floats2half2_rn(x.z - f23.x, x.w - f23.y);
            uint2 ho, lo;
            ho.x = *reinterpret_cast<unsigned int*>(&h01);
            ho.y = *reinterpret_cast<unsigned int*>(&h23);
            lo.x = *reinterpret_cast<unsigned int*>(&l01);
            lo.y = *reinterpret_cast<unsigned int*>(&l23);
            *(uint2*)&sWh[r * GS + c4] = ho;
            *(uint2*)&sWl[r * GS + c4] = lo;
        }
        __syncthreads();

#pragma unroll
        for (int kt = 0; kt < 2; kt++) {
            unsigned int ah[2][4], al[2][4];
#pragma unroll
            for (int mt = 0; mt < 2; mt++) {
                unsigned int off = (unsigned int)((a_off + mt * 16 * GS + kt * 16) * 2);
                ldsm_x4(ah_b + off, ah[mt][0], ah[mt][1], ah[mt][2], ah[mt][3]);
                ldsm_x4(al_b + off, al[mt][0], al[mt][1], al[mt][2], al[mt][3]);
            }
#pragma unroll
            for (int nt = 0; nt < 2; nt++) {
                unsigned int off = (unsigned int)((w_off + nt * 16 * GS + kt * 16) * 2);
                unsigned int wh0, wh1, wh2, wh3, wl0, wl1, wl2, wl3;
                ldsm_x4(wh_b + off, wh0, wh1, wh2, wh3);
                ldsm_x4(wl_b + off, wl0, wl1, wl2, wl3);
#pragma unroll
                for (int mt = 0; mt < 2; mt++) {
                    float* c0 = acc[mt][nt * 2 + 0];
                    float* c1 = acc[mt][nt * 2 + 1];
                    mma16816(c0, ah[mt][0], ah[mt][1], ah[mt][2], ah[mt][3], wh0, wh1);
                    mma16816(c1, ah[mt][0], ah[mt][1], ah[mt][2], ah[mt][3], wh2, wh3);
                    mma16816(c0, al[mt][0], al[mt][1], al[mt][2], al[mt][3], wh0, wh1);
                    mma16816(c1, al[mt][0], al[mt][1], al[mt][2], al[mt][3], wh2, wh3);
                    mma16816(c0, ah[mt][0], ah[mt][1], ah[mt][2], ah[mt][3], wl0, wl1);
                    mma16816(c1, ah[mt][0], ah[mt][1], ah[mt][2], ah[mt][3], wl2, wl3);
                }
            }
        }
    }

#pragma unroll
    for (int mt = 0; mt < 2; mt++) {
        int r = row0 + wm * 32 + mt * 16 + (lane >> 2);
#pragma unroll
        for (int n8 = 0; n8 < 4; n8++) {
            int c = col0 + wn * 32 + n8 * 8 + (lane & 3) * 2;
            float bx = bias[c], by = bias[c + 1];
            float2 f0, f1;
            f0.x = acc[mt][n8][0] + bx; f0.y = acc[mt][n8][1] + by;
            f1.x = acc[mt][n8][2] + bx; f1.y = acc[mt][n8][3] + by;
            *(float2*)&out[(size_t)r * CC + c] = f0;
            *(float2*)&out[(size_t)(r + 8) * CC + c] = f1;
        }
    }
}

// ---------------------------------------------------------------------------
// Fused converts: one launch covers Q-rope, K-rope, V-convert by block range.
// Q gets mult = QMULT (softmax scale * log2e folded in), K gets 1.0.
// ---------------------------------------------------------------------------
__device__ __forceinline__ void rope_one(const float* __restrict__ X,
                                         const int* __restrict__ pos,
                                         __half* __restrict__ dst, float mult, int idx)
{
    int a = idx % 3;
    int h = (idx / 3) % HH;
    int t = idx / (3 * HH);
    int b = t / NN, n = t % NN;

    float p = (float)pos[t * 3 + a];
    const float* x = X + (size_t)t * CC + h * HD + a * 16;

    float v[16];
#pragma unroll
    for (int c = 0; c < 4; c++) {
        float4 f = ((const float4*)x)[c];
        v[c * 4 + 0] = f.x; v[c * 4 + 1] = f.y; v[c * 4 + 2] = f.z; v[c * 4 + 3] = f.w;
    }

    const float LOG2_100 = 6.643856189774724f;
#pragma unroll
    for (int j = 0; j < 8; j++) {
        float inv = exp2f(-(float)j * 0.125f * LOG2_100);
        float ang = p * inv;
        float sn, cs;
        sincosf(ang, &sn, &cs);
        float x1 = v[j], x2 = v[j + 8];
        v[j]     = x1 * cs - x2 * sn;
        v[j + 8] = x2 * cs + x1 * sn;
    }

    unsigned int r[8];
#pragma unroll
    for (int i = 0; i < 8; i++) {
        __half2 h2 = __floats2half2_rn(v[2 * i] * mult, v[2 * i + 1] * mult);
        r[i] = *reinterpret_cast<unsigned int*>(&h2);
    }
    __half* d = dst + ((size_t)(b * HH + h) * NN + n) * HD + a * 16;
    uint4 o0 = {r[0], r[1], r[2], r[3]};
    uint4 o1 = {r[4], r[5], r[6], r[7]};
    ((uint4*)d)[0] = o0;
    ((uint4*)d)[1] = o1;
}

__global__ void cvt_all(const float* __restrict__ Q, const float* __restrict__ K,
                        const float* __restrict__ V,
                        const int* __restrict__ qpos, const int* __restrict__ kpos,
                        __half* __restrict__ Qh, __half* __restrict__ Kh,
                        __half* __restrict__ Vh)
{
    int blk = blockIdx.x;
    if (blk < 768) {
        rope_one(Q, qpos, Qh, QMULT, blk * 256 + threadIdx.x);
    } else if (blk < 1536) {
        rope_one(K, kpos, Kh, 1.0f, (blk - 768) * 256 + threadIdx.x);
    } else {
        int idx = (blk - 1536) * 256 + threadIdx.x;   // < TT*HH = 65536
        int h = idx % HH;
        int t = idx / HH;
        int b = t / NN, n = t % NN;
        const float* src = V + (size_t)t * CC + h * HD;
        __half* d = Vh + ((size_t)(b * HH + h) * NN + n) * HD;
#pragma unroll
        for (int c = 0; c < 6; c++) {
            float4 f0 = ((const float4*)src)[2 * c];
            float4 f1 = ((const float4*)src)[2 * c + 1];
            __half2 h0 = __floats2half2_rn(f0.x, f0.y);
            __half2 h1 = __floats2half2_rn(f0.z, f0.w);
            __half2 h2 = __floats2half2_rn(f1.x, f1.y);
            __half2 h3 = __floats2half2_rn(f1.z, f1.w);
            uint4 o;
            o.x = *reinterpret_cast<unsigned int*>(&h0);
            o.y = *reinterpret_cast<unsigned int*>(&h1);
            o.z = *reinterpret_cast<unsigned int*>(&h2);
            o.w = *reinterpret_cast<unsigned int*>(&h3);
            ((uint4*)d)[c] = o;
        }
    }
}

// ---------------------------------------------------------------------------
// Tensor-core flash attention.
// Block: 128 queries, 4 warps; warp = 32 query rows (two m16 fragments),
// so K/V ldmatrix fragments are loaded once and reused for both m-tiles.
// Key tiles of 64, double-buffered via cp.async. Softmax in exp2 domain
// (scale*log2e folded into Q); warp-vote skips the O-rescale when no new max.
// ---------------------------------------------------------------------------
#define ATS 56   // shared row stride in halfs (112B rows, 16B-aligned)
#define QT 128

__global__ __launch_bounds__(128) void attn_mma(const __half* __restrict__ Qh,
                                                const __half* __restrict__ Kh,
                                                const __half* __restrict__ Vh,
                                                float* __restrict__ X)
{
    __shared__ __half Qs[QT * ATS];
    __shared__ __half Ks[2][64 * ATS];
    __shared__ __half Vs[2][64 * ATS];

    int tid = threadIdx.x, lane = tid & 31, w = tid >> 5;
    int b = blockIdx.z, h = blockIdx.y;
    const size_t hb = ((size_t)(b * HH + h)) * NN * HD;
    int q0 = blockIdx.x * QT;

    unsigned int qs_base = (unsigned int)__cvta_generic_to_shared(Qs);
    unsigned int ks_base = (unsigned int)__cvta_generic_to_shared(&Ks[0][0]);
    unsigned int vs_base = (unsigned int)__cvta_generic_to_shared(&Vs[0][0]);
    const unsigned int BUFB = 64 * ATS * 2;  // buffer stride in bytes

    // Stage Q tile (128 x 48 halfs): 768 uint4 over 128 threads
    for (int e = tid; e < QT * 6; e += 128) {
        int r = e / 6, c = e % 6;
        *(uint4*)&Qs[r * ATS + c * 8] = *(const uint4*)(Qh + hb + (size_t)(q0 + r) * HD + c * 8);
    }

    // Prefetch K/V tile 0 into buffer 0
    for (int e = tid; e < 384; e += 128) {
        int r = e / 6, c = e % 6;
        size_t g = hb + (size_t)r * HD + c * 8;
        unsigned int so = (unsigned int)((r * ATS + c * 8) * 2);
        cp16(ks_base + so, Kh + g);
        cp16(vs_base + so, Vh + g);
    }
    CP_COMMIT();
    __syncthreads();

    // Q A-fragments: two m16 tiles per warp, persist across key tiles
    unsigned int qa[2][3][4];
#pragma unroll
    for (int mt = 0; mt < 2; mt++) {
        int arow = w * 32 + mt * 16 + (lane & 15);
        int acol = (lane >> 4) * 8;
#pragma unroll
        for (int k = 0; k < 3; k++) {
            unsigned int addr = qs_base + (unsigned int)((arow * ATS + k * 16 + acol) * 2);
            ldsm_x4(addr, qa[mt][k][0], qa[mt][k][1], qa[mt][k][2], qa[mt][k][3]);
        }
    }

    float o[2][6][4];
    float m[2][2], l[2][2];
#pragma unroll
    for (int mt = 0; mt < 2; mt++) {
        m[mt][0] = -1e30f; m[mt][1] = -1e30f;
        l[mt][0] = 0.f;    l[mt][1] = 0.f;
#pragma unroll
        for (int n = 0; n < 6; n++)
#pragma unroll
            for (int j = 0; j < 4; j++) o[mt][n][j] = 0.f;
    }

    int kb_off = ((lane & 7) + ((lane >> 4) & 1) * 8) * ATS + ((lane >> 3) & 1) * 8;
    int vb_off = ((lane & 7) + ((lane >> 3) & 1) * 8) * ATS + ((lane >> 4) & 1) * 8;

    const int NT = NN / 64;   // 32 tiles
    for (int kt = 0; kt < NT; kt++) {
        if (kt + 1 < NT) {
            unsigned int bo = ((kt + 1) & 1) * BUFB;
            for (int e = tid; e < 384; e += 128) {
                int r = e / 6, c = e % 6;
                size_t g = hb + (size_t)((kt + 1) * 64 + r) * HD + c * 8;
                unsigned int so = (unsigned int)((r * ATS + c * 8) * 2);
                cp16(ks_base + bo + so, Kh + g);
                cp16(vs_base + bo + so, Vh + g);
            }
            CP_COMMIT();
            CP_WAIT(1);
        } else {
            CP_WAIT(0);
        }
        __syncthreads();

        unsigned int bo = (kt & 1) * BUFB;

        // S = Q K^T (log2-domain scores; scale*log2e folded into Q)
        float s[2][8][4];
#pragma unroll
        for (int mt = 0; mt < 2; mt++)
#pragma unroll
            for (int n = 0; n < 8; n++)
#pragma unroll
                for (int j = 0; j < 4; j++) s[mt][n][j] = 0.f;

#pragma unroll
        for (int np = 0; np < 4; np++) {
#pragma unroll
            for (int k = 0; k < 3; k++) {
                unsigned int addr = ks_base + bo +
                    (unsigned int)(((np * 16) * ATS + k * 16 + kb_off) * 2);
                unsigned int b0, b1, b2, b3;
                ldsm_x4(addr, b0, b1, b2, b3);
#pragma unroll
                for (int mt = 0; mt < 2; mt++) {
                    mma16816(s[mt][2 * np],     qa[mt][k][0], qa[mt][k][1], qa[mt][k][2], qa[mt][k][3], b0, b1);
                    mma16816(s[mt][2 * np + 1], qa[mt][k][0], qa[mt][k][1], qa[mt][k][2], qa[mt][k][3], b2, b3);
                }
            }
        }

        // Tile maxima per row pair
        float tm[2][2];
#pragma unroll
        for (int mt = 0; mt < 2; mt++) {
            float t0 = s[mt][0][0], t1 = s[mt][0][2];
#pragma unroll
            for (int n = 0; n < 8; n++) {
                t0 = fmaxf(t0, fmaxf(s[mt][n][0], s[mt][n][1]));
                t1 = fmaxf(t1, fmaxf(s[mt][n][2], s[mt][n][3]));
            }
            t0 = fmaxf(t0, __shfl_xor_sync(0xffffffffu, t0, 1));
            t0 = fmaxf(t0, __shfl_xor_sync(0xffffffffu, t0, 2));
            t1 = fmaxf(t1, __shfl_xor_sync(0xffffffffu, t1, 1));
            t1 = fmaxf(t1, __shfl_xor_sync(0xffffffffu, t1, 2));
            tm[mt][0] = t0; tm[mt][1] = t1;
        }

        // Rescale only if some row in the warp saw a new max (warp-uniform branch)
        bool newmax = (tm[0][0] > m[0][0]) | (tm[0][1] > m[0][1]) |
                      (tm[1][0] > m[1][0]) | (tm[1][1] > m[1][1]);
        if (__any_sync(0xffffffffu, newmax)) {
#pragma unroll
            for (int mt = 0; mt < 2; mt++) {
                float nm0 = fmaxf(m[mt][0], tm[mt][0]);
                float nm1 = fmaxf(m[mt][1], tm[mt][1]);
                float al0 = ex2f(m[mt][0] - nm0);
                float al1 = ex2f(m[mt][1] - nm1);
                m[mt][0] = nm0; m[mt][1] = nm1;
                l[mt][0] *= al0; l[mt][1] *= al1;
#pragma unroll
                for (int n = 0; n < 6; n++) {
                    o[mt][n][0] *= al0; o[mt][n][1] *= al0;
                    o[mt][n][2] *= al1; o[mt][n][3] *= al1;
                }
            }
        }

        // p = 2^(s - m); accumulate l
#pragma unroll
        for (int mt = 0; mt < 2; mt++) {
            float l0 = 0.f, l1 = 0.f;
#pragma unroll
            for (int n = 0; n < 8; n++) {
                s[mt][n][0] = ex2f(s[mt][n][0] - m[mt][0]);
                s[mt][n][1] = ex2f(s[mt][n][1] - m[mt][0]);
                s[mt][n][2] = ex2f(s[mt][n][2] - m[mt][1]);
                s[mt][n][3] = ex2f(s[mt][n][3] - m[mt][1]);
                l0 += s[mt][n][0] + s[mt][n][1];
                l1 += s[mt][n][2] + s[mt][n][3];
            }
            l[mt][0] += l0; l[mt][1] += l1;
        }

        // O += P V (V fragments shared across both m-tiles)
#pragma unroll
        for (int k4 = 0; k4 < 4; k4++) {
            unsigned int a[2][4];
#pragma unroll
            for (int mt = 0; mt < 2; mt++) {
                a[mt][0] = packh2(s[mt][2 * k4][0],     s[mt][2 * k4][1]);
                a[mt][1] = packh2(s[mt][2 * k4][2],     s[mt][2 * k4][3]);
                a[mt][2] = packh2(s[mt][2 * k4 + 1][0], s[mt][2 * k4 + 1][1]);
                a[mt][3] = packh2(s[mt][2 * k4 + 1][2], s[mt][2 * k4 + 1][3]);
            }
#pragma unroll
            for (int np = 0; np < 3; np++) {
                unsigned int addr = vs_base + bo +
                    (unsigned int)(((k4 * 16) * ATS + np * 16 + vb_off) * 2);
                unsigned int b0, b1, b2, b3;
                ldsm_x4_t(addr, b0, b1, b2, b3);
#pragma unroll
                for (int mt = 0; mt < 2; mt++) {
                    mma16816(o[mt][2 * np],     a[mt][0], a[mt][1], a[mt][2], a[mt][3], b0, b1);
                    mma16816(o[mt][2 * np + 1], a[mt][0], a[mt][1], a[mt][2], a[mt][3], b2, b3);
                }
            }
        }
        __syncthreads();
    }

    // Final normalize + write (token-major fp32 for the output GEMM)
#pragma unroll
    for (int mt = 0; mt < 2; mt++) {
        float l0 = l[mt][0], l1 = l[mt][1];
        l0 += __shfl_xor_sync(0xffffffffu, l0, 1);
        l0 += __shfl_xor_sync(0xffffffffu, l0, 2);
        l1 += __shfl_xor_sync(0xffffffffu, l1, 1);
        l1 += __shfl_xor_sync(0xffffffffu, l1, 2);
        float i0 = 1.f / l0, i1 = 1.f / l1;

        int r0 = q0 + w * 32 + mt * 16 + (lane >> 2);
        int cbase = h * HD + (lane & 3) * 2;
#pragma unroll
        for (int n = 0; n < 6; n++) {
            float2 f0; f0.x = o[mt][n][0] * i0; f0.y = o[mt][n][1] * i0;
            float2 f1; f1.x = o[mt][n][2] * i1; f1.y = o[mt][n][3] * i1;
            *(float2*)&X[(size_t)(b * NN + r0) * CC + cbase + n * 8] = f0;
            *(float2*)&X[(size_t)(b * NN + r0 + 8) * CC + cbase + n * 8] = f1;
        }
    }
}

// ---------------------------------------------------------------------------
// Launch
// ---------------------------------------------------------------------------
extern "C" void kernel_launch(void* const* d_in, const int* in_sizes, int n_in,
                              void* d_out, int out_size)
{
    const float* query = (const float*)d_in[0];
    const float* key   = (const float*)d_in[1];
    const float* value = (const float*)d_in[2];
    const float* Wq = (const float*)d_in[3];
    const float* bq = (const float*)d_in[4];
    const float* Wk = (const float*)d_in[5];
    const float* bk = (const float*)d_in[6];
    const float* Wv = (const float*)d_in[7];
    const float* bv = (const float*)d_in[8];
    const float* Wo = (const float*)d_in[9];
    const float* bo = (const float*)d_in[10];
    const int* qpos = (const int*)d_in[11];
    const int* kpos = (const int*)d_in[12];
    float* out = (float*)d_out;

    float *pQ, *pK, *pV, *pX;
    __half *pQh, *pKh, *pVh;
    cudaGetSymbolAddress((void**)&pQ, g_Q);
    cudaGetSymbolAddress((void**)&pK, g_K);
    cudaGetSymbolAddress((void**)&pV, g_V);
    cudaGetSymbolAddress((void**)&pX, g_X);
    cudaGetSymbolAddress((void**)&pQh, g_Qh);
    cudaGetSymbolAddress((void**)&pKh, g_Kh);
    cudaGetSymbolAddress((void**)&pVh, g_Vh);

    dim3 ggrid(CC / 64, TT / 128);   // (6, 64)

    gemm_h3f<<<ggrid, 256>>>(query, Wq, bq, pQ);
    gemm_h3f<<<ggrid, 256>>>(key,   Wk, bk, pK);
    gemm_h3f<<<ggrid, 256>>>(value, Wv, bv, pV);

    // Q-rope (768 blocks) + K-rope (768) + V-convert (256) in one launch
    cvt_all<<<1792, 256>>>(pQ, pK, pV, qpos, kpos, pQh, pKh, pVh);

    attn_mma<<<dim3(NN / QT, HH, BB), 128>>>(pQh, pKh, pVh, pX);

    gemm_h3f<<<ggrid, 256>>>(pX, Wo, bo, out);
}

// round 10
// speedup vs baseline: 1.2803x; 1.2142x over previous
#include <cuda_runtime.h>
#include <cuda_fp16.h>
#include <math.h>

// Problem constants
#define BB 4
#define NN 2048
#define CC 384
#define HH 8
#define HD 48
#define TT (BB * NN)          // 8192 tokens
#define SCALE 0.14433756729740645f       // 1/sqrt(48)
#define QMULT 0.20823444283700469f       // SCALE * log2(e)

// Scratch (static device globals — no runtime allocation)
__device__ float g_Q[TT * CC];
__device__ float g_K[TT * CC];
__device__ float g_V[TT * CC];
__device__ float g_X[TT * CC];
__device__ __half g_Qh[TT * CC];   // head-major: [B][H][N][HD]
__device__ __half g_Kh[TT * CC];
__device__ __half g_Vh[TT * CC];

// ---------------------------------------------------------------------------
// MMA / async-copy helpers
// ---------------------------------------------------------------------------
__device__ __forceinline__ void ldsm_x4(unsigned int addr, unsigned int& r0,
                                        unsigned int& r1, unsigned int& r2, unsigned int& r3)
{
    asm volatile("ldmatrix.sync.aligned.m8n8.x4.shared.b16 {%0,%1,%2,%3}, [%4];"
                 : "=r"(r0), "=r"(r1), "=r"(r2), "=r"(r3) : "r"(addr));
}
__device__ __forceinline__ void ldsm_x4_t(unsigned int addr, unsigned int& r0,
                                          unsigned int& r1, unsigned int& r2, unsigned int& r3)
{
    asm volatile("ldmatrix.sync.aligned.m8n8.x4.trans.shared.b16 {%0,%1,%2,%3}, [%4];"
                 : "=r"(r0), "=r"(r1), "=r"(r2), "=r"(r3) : "r"(addr));
}
__device__ __forceinline__ void mma16816(float* c, unsigned int a0, unsigned int a1,
                                         unsigned int a2, unsigned int a3,
                                         unsigned int b0, unsigned int b1)
{
    asm volatile("mma.sync.aligned.m16n8k16.row.col.f32.f16.f16.f32 "
                 "{%0,%1,%2,%3}, {%4,%5,%6,%7}, {%8,%9}, {%0,%1,%2,%3};"
                 : "+f"(c[0]), "+f"(c[1]), "+f"(c[2]), "+f"(c[3])
                 : "r"(a0), "r"(a1), "r"(a2), "r"(a3), "r"(b0), "r"(b1));
}
__device__ __forceinline__ unsigned int packh2(float x, float y)
{
    __half2 h = __floats2half2_rn(x, y);
    return *reinterpret_cast<unsigned int*>(&h);
}
__device__ __forceinline__ float ex2f(float x)
{
    float r; asm("ex2.approx.ftz.f32 %0, %1;" : "=f"(r) : "f"(x)); return r;
}
__device__ __forceinline__ void cp16(unsigned int saddr, const void* gptr)
{
    asm volatile("cp.async.cg.shared.global [%0], [%1], 16;" :: "r"(saddr), "l"(gptr));
}
#define CP_COMMIT() asm volatile("cp.async.commit_group;")
#define CP_WAIT(n)  asm volatile("cp.async.wait_group %0;" :: "n"(n))

// ---------------------------------------------------------------------------
// Split-fp16 tensor-core GEMM, fused fp32->(hi,lo) conversion, register-
// prefetch pipelined staging, and up-to-3-way batch via blockIdx.z.
// out[m][n] = sum_k A[m][k]*W[n][k] + bias[n].
// CTA tile 128x64, BK=32, 8 warps (4 m x 2 n, 32x32 per warp).
// ---------------------------------------------------------------------------
#define GS 40   // shared row stride in halfs (80B: conflict-free ldmatrix)

__global__ __launch_bounds__(256) void gemm_h3p(const float* __restrict__ A0,
                                                const float* __restrict__ A1,
                                                const float* __restrict__ A2,
                                                const float* __restrict__ W0,
                                                const float* __restrict__ W1,
                                                const float* __restrict__ W2,
                                                const float* __restrict__ b0,
                                                const float* __restrict__ b1,
                                                const float* __restrict__ b2,
                                                float* __restrict__ o0,
                                                float* __restrict__ o1,
                                                float* __restrict__ o2)
{
    const float* A    = blockIdx.z == 0 ? A0 : (blockIdx.z == 1 ? A1 : A2);
    const float* W    = blockIdx.z == 0 ? W0 : (blockIdx.z == 1 ? W1 : W2);
    const float* bias = blockIdx.z == 0 ? b0 : (blockIdx.z == 1 ? b1 : b2);
    float* out        = blockIdx.z == 0 ? o0 : (blockIdx.z == 1 ? o1 : o2);

    __shared__ __half sAh[128 * GS];
    __shared__ __half sAl[128 * GS];
    __shared__ __half sWh[64 * GS];
    __shared__ __half sWl[64 * GS];

    int tid = threadIdx.x, lane = tid & 31, warp = tid >> 5;
    int wm = warp & 3, wn = warp >> 2;
    int row0 = blockIdx.y * 128;
    int col0 = blockIdx.x * 64;

    float acc[2][4][4];
#pragma unroll
    for (int mt = 0; mt < 2; mt++)
#pragma unroll
        for (int n8 = 0; n8 < 4; n8++)
#pragma unroll
            for (int j = 0; j < 4; j++) acc[mt][n8][j] = 0.f;

    unsigned int ah_b = (unsigned int)__cvta_generic_to_shared(sAh);
    unsigned int al_b = (unsigned int)__cvta_generic_to_shared(sAl);
    unsigned int wh_b = (unsigned int)__cvta_generic_to_shared(sWh);
    unsigned int wl_b = (unsigned int)__cvta_generic_to_shared(sWl);

    int a_off = (wm * 32 + (lane & 15)) * GS + (lane >> 4) * 8;
    int w_off = (wn * 32 + (lane & 7) + ((lane >> 4) & 1) * 8) * GS + ((lane >> 3) & 1) * 8;

    // Per-thread staging coordinates
    int ar = tid >> 1, ac4 = (tid & 1) * 16;      // A: 128 rows x 2 threads (2 float4 each)
    int wr = tid >> 2, wc4 = (tid & 3) * 8;       // W: 64 rows x 4 threads (1 float4... ) 
    // A: each thread loads 2 float4 (rows ar, cols ac4..ac4+7? no). Use prior scheme:
    // A: 1024 float4 -> 4 per thread; W: 512 float4 -> 2 per thread.

    float4 ra[4], rw[2];
#pragma unroll
    for (int p = 0; p < 4; p++) {
        int e = tid + p * 256;
        int r = e >> 3, c4 = (e & 7) * 4;
        ra[p] = *(const float4*)(A + (size_t)(row0 + r) * CC + c4);
    }
#pragma unroll
    for (int p = 0; p < 2; p++) {
        int e = tid + p * 256;
        int r = e >> 3, c4 = (e & 7) * 4;
        rw[p] = *(const float4*)(W + (size_t)(col0 + r) * CC + c4);
    }

    for (int k0 = 0; k0 < CC; k0 += 32) {
        __syncthreads();
        // Store prefetched tile (convert to hi/lo planes)
#pragma unroll
        for (int p = 0; p < 4; p++) {
            int e = tid + p * 256;
            int r = e >> 3, c4 = (e & 7) * 4;
            float4 x = ra[p];
            __half2 h01 = __floats2half2_rn(x.x, x.y);
            __half2 h23 = __floats2half2_rn(x.z, x.w);
            float2 f01 = __half22float2(h01);
            float2 f23 = __half22float2(h23);
            __half2 l01 = __floats2half2_rn(x.x - f01.x, x.y - f01.y);
            __half2 l23 = __floats2half2_rn(x.z - f23.x, x.w - f23.y);
            uint2 ho, lo;
            ho.x = *reinterpret_cast<unsigned int*>(&h01);
            ho.y = *reinterpret_cast<unsigned int*>(&h23);
            lo.x = *reinterpret_cast<unsigned int*>(&l01);
            lo.y = *reinterpret_cast<unsigned int*>(&l23);
            *(uint2*)&sAh[r * GS + c4] = ho;
            *(uint2*)&sAl[r * GS + c4] = lo;
        }
#pragma unroll
        for (int p = 0; p < 2; p++) {
            int e = tid + p * 256;
            int r = e >> 3, c4 = (e & 7) * 4;
            float4 x = rw[p];
            __half2 h01 = __floats2half2_rn(x.x, x.y);
            __half2 h23 = __floats2half2_rn(x.z, x.w);
            float2 f01 = __half22float2(h01);
            float2 f23 = __half22float2(h23);
            __half2 l01 = __floats2half2_rn(x.x - f01.x, x.y - f01.y);
            __half2 l23 = __floats2half2_rn(x.z - f23.x, x.w - f23.y);
            uint2 ho, lo;
            ho.x = *reinterpret_cast<unsigned int*>(&h01);
            ho.y = *reinterpret_cast<unsigned int*>(&h23);
            lo.x = *reinterpret_cast<unsigned int*>(&l01);
            lo.y = *reinterpret_cast<unsigned int*>(&l23);
            *(uint2*)&sWh[r * GS + c4] = ho;
            *(uint2*)&sWl[r * GS + c4] = lo;
        }
        __syncthreads();

        // Prefetch next k-tile into registers (overlaps with MMA below)
        if (k0 + 32 < CC) {
#pragma unroll
            for (int p = 0; p < 4; p++) {
                int e = tid + p * 256;
                int r = e >> 3, c4 = (e & 7) * 4;
                ra[p] = *(const float4*)(A + (size_t)(row0 + r) * CC + k0 + 32 + c4);
            }
#pragma unroll
            for (int p = 0; p < 2; p++) {
                int e = tid + p * 256;
                int r = e >> 3, c4 = (e & 7) * 4;
                rw[p] = *(const float4*)(W + (size_t)(col0 + r) * CC + k0 + 32 + c4);
            }
        }

#pragma unroll
        for (int kt = 0; kt < 2; kt++) {
            unsigned int ah[2][4], al[2][4];
#pragma unroll
            for (int mt = 0; mt < 2; mt++) {
                unsigned int off = (unsigned int)((a_off + mt * 16 * GS + kt * 16) * 2);
                ldsm_x4(ah_b + off, ah[mt][0], ah[mt][1], ah[mt][2], ah[mt][3]);
                ldsm_x4(al_b + off, al[mt][0], al[mt][1], al[mt][2], al[mt][3]);
            }
#pragma unroll
            for (int nt = 0; nt < 2; nt++) {
                unsigned int off = (unsigned int)((w_off + nt * 16 * GS + kt * 16) * 2);
                unsigned int wh0, wh1, wh2, wh3, wl0, wl1, wl2, wl3;
                ldsm_x4(wh_b + off, wh0, wh1, wh2, wh3);
                ldsm_x4(wl_b + off, wl0, wl1, wl2, wl3);
#pragma unroll
                for (int mt = 0; mt < 2; mt++) {
                    float* c0 = acc[mt][nt * 2 + 0];
                    float* c1 = acc[mt][nt * 2 + 1];
                    mma16816(c0, ah[mt][0], ah[mt][1], ah[mt][2], ah[mt][3], wh0, wh1);
                    mma16816(c1, ah[mt][0], ah[mt][1], ah[mt][2], ah[mt][3], wh2, wh3);
                    mma16816(c0, al[mt][0], al[mt][1], al[mt][2], al[mt][3], wh0, wh1);
                    mma16816(c1, al[mt][0], al[mt][1], al[mt][2], al[mt][3], wh2, wh3);
                    mma16816(c0, ah[mt][0], ah[mt][1], ah[mt][2], ah[mt][3], wl0, wl1);
                    mma16816(c1, ah[mt][0], ah[mt][1], ah[mt][2], ah[mt][3], wl2, wl3);
                }
            }
        }
    }

#pragma unroll
    for (int mt = 0; mt < 2; mt++) {
        int r = row0 + wm * 32 + mt * 16 + (lane >> 2);
#pragma unroll
        for (int n8 = 0; n8 < 4; n8++) {
            int c = col0 + wn * 32 + n8 * 8 + (lane & 3) * 2;
            float bx = bias[c], by = bias[c + 1];
            float2 f0, f1;
            f0.x = acc[mt][n8][0] + bx; f0.y = acc[mt][n8][1] + by;
            f1.x = acc[mt][n8][2] + bx; f1.y = acc[mt][n8][3] + by;
            *(float2*)&out[(size_t)r * CC + c] = f0;
            *(float2*)&out[(size_t)(r + 8) * CC + c] = f1;
        }
    }
}

// ---------------------------------------------------------------------------
// Fused converts: one launch covers Q-rope, K-rope, V-convert by block range.
// ---------------------------------------------------------------------------
__device__ __forceinline__ void rope_one(const float* __restrict__ X,
                                         const int* __restrict__ pos,
                                         __half* __restrict__ dst, float mult, int idx)
{
    int a = idx % 3;
    int h = (idx / 3) % HH;
    int t = idx / (3 * HH);
    int b = t / NN, n = t % NN;

    float p = (float)pos[t * 3 + a];
    const float* x = X + (size_t)t * CC + h * HD + a * 16;

    float v[16];
#pragma unroll
    for (int c = 0; c < 4; c++) {
        float4 f = ((const float4*)x)[c];
        v[c * 4 + 0] = f.x; v[c * 4 + 1] = f.y; v[c * 4 + 2] = f.z; v[c * 4 + 3] = f.w;
    }

    const float LOG2_100 = 6.643856189774724f;
#pragma unroll
    for (int j = 0; j < 8; j++) {
        float inv = exp2f(-(float)j * 0.125f * LOG2_100);
        float ang = p * inv;
        float sn, cs;
        sincosf(ang, &sn, &cs);
        float x1 = v[j], x2 = v[j + 8];
        v[j]     = x1 * cs - x2 * sn;
        v[j + 8] = x2 * cs + x1 * sn;
    }

    unsigned int r[8];
#pragma unroll
    for (int i = 0; i < 8; i++) {
        __half2 h2 = __floats2half2_rn(v[2 * i] * mult, v[2 * i + 1] * mult);
        r[i] = *reinterpret_cast<unsigned int*>(&h2);
    }
    __half* d = dst + ((size_t)(b * HH + h) * NN + n) * HD + a * 16;
    uint4 o0 = {r[0], r[1], r[2], r[3]};
    uint4 o1 = {r[4], r[5], r[6], r[7]};
    ((uint4*)d)[0] = o0;
    ((uint4*)d)[1] = o1;
}

__global__ void cvt_all(const float* __restrict__ Q, const float* __restrict__ K,
                        const float* __restrict__ V,
                        const int* __restrict__ qpos, const int* __restrict__ kpos,
                        __half* __restrict__ Qh, __half* __restrict__ Kh,
                        __half* __restrict__ Vh)
{
    int blk = blockIdx.x;
    if (blk < 768) {
        rope_one(Q, qpos, Qh, QMULT, blk * 256 + threadIdx.x);
    } else if (blk < 1536) {
        rope_one(K, kpos, Kh, 1.0f, (blk - 768) * 256 + threadIdx.x);
    } else {
        int idx = (blk - 1536) * 256 + threadIdx.x;   // < TT*HH = 65536
        int h = idx % HH;
        int t = idx / HH;
        int b = t / NN, n = t % NN;
        const float* src = V + (size_t)t * CC + h * HD;
        __half* d = Vh + ((size_t)(b * HH + h) * NN + n) * HD;
#pragma unroll
        for (int c = 0; c < 6; c++) {
            float4 f0 = ((const float4*)src)[2 * c];
            float4 f1 = ((const float4*)src)[2 * c + 1];
            __half2 h0 = __floats2half2_rn(f0.x, f0.y);
            __half2 h1 = __floats2half2_rn(f0.z, f0.w);
            __half2 h2 = __floats2half2_rn(f1.x, f1.y);
            __half2 h3 = __floats2half2_rn(f1.z, f1.w);
            uint4 o;
            o.x = *reinterpret_cast<unsigned int*>(&h0);
            o.y = *reinterpret_cast<unsigned int*>(&h1);
            o.z = *reinterpret_cast<unsigned int*>(&h2);
            o.w = *reinterpret_cast<unsigned int*>(&h3);
            ((uint4*)d)[c] = o;
        }
    }
}

// ---------------------------------------------------------------------------
// Tensor-core flash attention (validated R9).
// 128 queries, 4 warps; warp = 32 query rows (two m16 fragments).
// Key tiles of 64, double-buffered cp.async; exp2-domain softmax;
// warp-vote rescale skip.
// ---------------------------------------------------------------------------
#define ATS 56
#define QT 128

__global__ __launch_bounds__(128) void attn_mma(const __half* __restrict__ Qh,
                                                const __half* __restrict__ Kh,
                                                const __half* __restrict__ Vh,
                                                float* __restrict__ X)
{
    __shared__ __half Qs[QT * ATS];
    __shared__ __half Ks[2][64 * ATS];
    __shared__ __half Vs[2][64 * ATS];

    int tid = threadIdx.x, lane = tid & 31, w = tid >> 5;
    int b = blockIdx.z, h = blockIdx.y;
    const size_t hb = ((size_t)(b * HH + h)) * NN * HD;
    int q0 = blockIdx.x * QT;

    unsigned int qs_base = (unsigned int)__cvta_generic_to_shared(Qs);
    unsigned int ks_base = (unsigned int)__cvta_generic_to_shared(&Ks[0][0]);
    unsigned int vs_base = (unsigned int)__cvta_generic_to_shared(&Vs[0][0]);
    const unsigned int BUFB = 64 * ATS * 2;

    for (int e = tid; e < QT * 6; e += 128) {
        int r = e / 6, c = e % 6;
        *(uint4*)&Qs[r * ATS + c * 8] = *(const uint4*)(Qh + hb + (size_t)(q0 + r) * HD + c * 8);
    }

    for (int e = tid; e < 384; e += 128) {
        int r = e / 6, c = e % 6;
        size_t g = hb + (size_t)r * HD + c * 8;
        unsigned int so = (unsigned int)((r * ATS + c * 8) * 2);
        cp16(ks_base + so, Kh + g);
        cp16(vs_base + so, Vh + g);
    }
    CP_COMMIT();
    __syncthreads();

    unsigned int qa[2][3][4];
#pragma unroll
    for (int mt = 0; mt < 2; mt++) {
        int arow = w * 32 + mt * 16 + (lane & 15);
        int acol = (lane >> 4) * 8;
#pragma unroll
        for (int k = 0; k < 3; k++) {
            unsigned int addr = qs_base + (unsigned int)((arow * ATS + k * 16 + acol) * 2);
            ldsm_x4(addr, qa[mt][k][0], qa[mt][k][1], qa[mt][k][2], qa[mt][k][3]);
        }
    }

    float o[2][6][4];
    float m[2][2], l[2][2];
#pragma unroll
    for (int mt = 0; mt < 2; mt++) {
        m[mt][0] = -1e30f; m[mt][1] = -1e30f;
        l[mt][0] = 0.f;    l[mt][1] = 0.f;
#pragma unroll
        for (int n = 0; n < 6; n++)
#pragma unroll
            for (int j = 0; j < 4; j++) o[mt][n][j] = 0.f;
    }

    int kb_off = ((lane & 7) + ((lane >> 4) & 1) * 8) * ATS + ((lane >> 3) & 1) * 8;
    int vb_off = ((lane & 7) + ((lane >> 3) & 1) * 8) * ATS + ((lane >> 4) & 1) * 8;

    const int NT = NN / 64;
    for (int kt = 0; kt < NT; kt++) {
        if (kt + 1 < NT) {
            unsigned int bo = ((kt + 1) & 1) * BUFB;
            for (int e = tid; e < 384; e += 128) {
                int r = e / 6, c = e % 6;
                size_t g = hb + (size_t)((kt + 1) * 64 + r) * HD + c * 8;
                unsigned int so = (unsigned int)((r * ATS + c * 8) * 2);
                cp16(ks_base + bo + so, Kh + g);
                cp16(vs_base + bo + so, Vh + g);
            }
            CP_COMMIT();
            CP_WAIT(1);
        } else {
            CP_WAIT(0);
        }
        __syncthreads();

        unsigned int bo = (kt & 1) * BUFB;

        float s[2][8][4];
#pragma unroll
        for (int mt = 0; mt < 2; mt++)
#pragma unroll
            for (int n = 0; n < 8; n++)
#pragma unroll
                for (int j = 0; j < 4; j++) s[mt][n][j] = 0.f;

#pragma unroll
        for (int np = 0; np < 4; np++) {
#pragma unroll
            for (int k = 0; k < 3; k++) {
                unsigned int addr = ks_base + bo +
                    (unsigned int)(((np * 16) * ATS + k * 16 + kb_off) * 2);
                unsigned int b0, b1, b2, b3;
                ldsm_x4(addr, b0, b1, b2, b3);
#pragma unroll
                for (int mt = 0; mt < 2; mt++) {
                    mma16816(s[mt][2 * np],     qa[mt][k][0], qa[mt][k][1], qa[mt][k][2], qa[mt][k][3], b0, b1);
                    mma16816(s[mt][2 * np + 1], qa[mt][k][0], qa[mt][k][1], qa[mt][k][2], qa[mt][k][3], b2, b3);
                }
            }
        }

        float tm[2][2];
#pragma unroll
        for (int mt = 0; mt < 2; mt++) {
            float t0 = s[mt][0][0], t1 = s[mt][0][2];
#pragma unroll
            for (int n = 0; n < 8; n++) {
                t0 = fmaxf(t0, fmaxf(s[mt][n][0], s[mt][n][1]));
                t1 = fmaxf(t1, fmaxf(s[mt][n][2], s[mt][n][3]));
            }
            t0 = fmaxf(t0, __shfl_xor_sync(0xffffffffu, t0, 1));
            t0 = fmaxf(t0, __shfl_xor_sync(0xffffffffu, t0, 2));
            t1 = fmaxf(t1, __shfl_xor_sync(0xffffffffu, t1, 1));
            t1 = fmaxf(t1, __shfl_xor_sync(0xffffffffu, t1, 2));
            tm[mt][0] = t0; tm[mt][1] = t1;
        }

        bool newmax = (tm[0][0] > m[0][0]) | (tm[0][1] > m[0][1]) |
                      (tm[1][0] > m[1][0]) | (tm[1][1] > m[1][1]);
        if (__any_sync(0xffffffffu, newmax)) {
#pragma unroll
            for (int mt = 0; mt < 2; mt++) {
                float nm0 = fmaxf(m[mt][0], tm[mt][0]);
                float nm1 = fmaxf(m[mt][1], tm[mt][1]);
                float al0 = ex2f(m[mt][0] - nm0);
                float al1 = ex2f(m[mt][1] - nm1);
                m[mt][0] = nm0; m[mt][1] = nm1;
                l[mt][0] *= al0; l[mt][1] *= al1;
#pragma unroll
                for (int n = 0; n < 6; n++) {
                    o[mt][n][0] *= al0; o[mt][n][1] *= al0;
                    o[mt][n][2] *= al1; o[mt][n][3] *= al1;
                }
            }
        }

#pragma unroll
        for (int mt = 0; mt < 2; mt++) {
            float l0 = 0.f, l1 = 0.f;
#pragma unroll
            for (int n = 0; n < 8; n++) {
                s[mt][n][0] = ex2f(s[mt][n][0] - m[mt][0]);
                s[mt][n][1] = ex2f(s[mt][n][1] - m[mt][0]);
                s[mt][n][2] = ex2f(s[mt][n][2] - m[mt][1]);
                s[mt][n][3] = ex2f(s[mt][n][3] - m[mt][1]);
                l0 += s[mt][n][0] + s[mt][n][1];
                l1 += s[mt][n][2] + s[mt][n][3];
            }
            l[mt][0] += l0; l[mt][1] += l1;
        }

#pragma unroll
        for (int k4 = 0; k4 < 4; k4++) {
            unsigned int a[2][4];
#pragma unroll
            for (int mt = 0; mt < 2; mt++) {
                a[mt][0] = packh2(s[mt][2 * k4][0],     s[mt][2 * k4][1]);
                a[mt][1] = packh2(s[mt][2 * k4][2],     s[mt][2 * k4][3]);
                a[mt][2] = packh2(s[mt][2 * k4 + 1][0], s[mt][2 * k4 + 1][1]);
                a[mt][3] = packh2(s[mt][2 * k4 + 1][2], s[mt][2 * k4 + 1][3]);
            }
#pragma unroll
            for (int np = 0; np < 3; np++) {
                unsigned int addr = vs_base + bo +
                    (unsigned int)(((k4 * 16) * ATS + np * 16 + vb_off) * 2);
                unsigned int b0, b1, b2, b3;
                ldsm_x4_t(addr, b0, b1, b2, b3);
#pragma unroll
                for (int mt = 0; mt < 2; mt++) {
                    mma16816(o[mt][2 * np],     a[mt][0], a[mt][1], a[mt][2], a[mt][3], b0, b1);
                    mma16816(o[mt][2 * np + 1], a[mt][0], a[mt][1], a[mt][2], a[mt][3], b2, b3);
                }
            }
        }
        __syncthreads();
    }

#pragma unroll
    for (int mt = 0; mt < 2; mt++) {
        float l0 = l[mt][0], l1 = l[mt][1];
        l0 += __shfl_xor_sync(0xffffffffu, l0, 1);
        l0 += __shfl_xor_sync(0xffffffffu, l0, 2);
        l1 += __shfl_xor_sync(0xffffffffu, l1, 1);
        l1 += __shfl_xor_sync(0xffffffffu, l1, 2);
        float i0 = 1.f / l0, i1 = 1.f / l1;

        int r0 = q0 + w * 32 + mt * 16 + (lane >> 2);
        int cbase = h * HD + (lane & 3) * 2;
#pragma unroll
        for (int n = 0; n < 6; n++) {
            float2 f0; f0.x = o[mt][n][0] * i0; f0.y = o[mt][n][1] * i0;
            float2 f1; f1.x = o[mt][n][2] * i1; f1.y = o[mt][n][3] * i1;
            *(float2*)&X[(size_t)(b * NN + r0) * CC + cbase + n * 8] = f0;
            *(float2*)&X[(size_t)(b * NN + r0 + 8) * CC + cbase + n * 8] = f1;
        }
    }
}

// ---------------------------------------------------------------------------
// Launch
// ---------------------------------------------------------------------------
extern "C" void kernel_launch(void* const* d_in, const int* in_sizes, int n_in,
                              void* d_out, int out_size)
{
    const float* query = (const float*)d_in[0];
    const float* key   = (const float*)d_in[1];
    const float* value = (const float*)d_in[2];
    const float* Wq = (const float*)d_in[3];
    const float* bq = (const float*)d_in[4];
    const float* Wk = (const float*)d_in[5];
    const float* bk = (const float*)d_in[6];
    const float* Wv = (const float*)d_in[7];
    const float* bv = (const float*)d_in[8];
    const float* Wo = (const float*)d_in[9];
    const float* bo = (const float*)d_in[10];
    const int* qpos = (const int*)d_in[11];
    const int* kpos = (const int*)d_in[12];
    float* out = (float*)d_out;

    float *pQ, *pK, *pV, *pX;
    __half *pQh, *pKh, *pVh;
    cudaGetSymbolAddress((void**)&pQ, g_Q);
    cudaGetSymbolAddress((void**)&pK, g_K);
    cudaGetSymbolAddress((void**)&pV, g_V);
    cudaGetSymbolAddress((void**)&pX, g_X);
    cudaGetSymbolAddress((void**)&pQh, g_Qh);
    cudaGetSymbolAddress((void**)&pKh, g_Kh);
    cudaGetSymbolAddress((void**)&pVh, g_Vh);

    // Q/K/V projections in ONE launch (blockIdx.z selects the triple)
    dim3 g3(CC / 64, TT / 128, 3);   // (6, 64, 3) = 1152 CTAs
    gemm_h3p<<<g3, 256>>>(query, key, value,
                          Wq, Wk, Wv,
                          bq, bk, bv,
                          pQ, pK, pV);

    // Q-rope + K-rope + V-convert in one launch
    cvt_all<<<1792, 256>>>(pQ, pK, pV, qpos, kpos, pQh, pKh, pVh);

    attn_mma<<<dim3(NN / QT, HH, BB), 128>>>(pQh, pKh, pVh, pX);

    // Output projection (single-matrix use of the same kernel)
    dim3 g1(CC / 64, TT / 128, 1);
    gemm_h3p<<<g1, 256>>>(pX, pX, pX,
                          Wo, Wo, Wo,
                          bo, bo, bo,
                          out, out, out);
}

// round 11
// speedup vs baseline: 1.3158x; 1.0277x over previous
#include <cuda_runtime.h>
#include <cuda_fp16.h>
#include <math.h>

// Problem constants
#define BB 4
#define NN 2048
#define CC 384
#define HH 8
#define HD 48
#define TT (BB * NN)          // 8192 tokens
#define SCALE 0.14433756729740645f       // 1/sqrt(48)
#define QMULT 0.20823444283700469f       // SCALE * log2(e)

// Scratch (static device globals — no runtime allocation)
__device__ float g_X[TT * CC];
__device__ __half g_Qh[TT * CC];   // head-major: [B][H][N][HD]
__device__ __half g_Kh[TT * CC];
__device__ __half g_Vh[TT * CC];

// ---------------------------------------------------------------------------
// MMA / async-copy helpers
// ---------------------------------------------------------------------------
__device__ __forceinline__ void ldsm_x4(unsigned int addr, unsigned int& r0,
                                        unsigned int& r1, unsigned int& r2, unsigned int& r3)
{
    asm volatile("ldmatrix.sync.aligned.m8n8.x4.shared.b16 {%0,%1,%2,%3}, [%4];"
                 : "=r"(r0), "=r"(r1), "=r"(r2), "=r"(r3) : "r"(addr));
}
__device__ __forceinline__ void ldsm_x4_t(unsigned int addr, unsigned int& r0,
                                          unsigned int& r1, unsigned int& r2, unsigned int& r3)
{
    asm volatile("ldmatrix.sync.aligned.m8n8.x4.trans.shared.b16 {%0,%1,%2,%3}, [%4];"
                 : "=r"(r0), "=r"(r1), "=r"(r2), "=r"(r3) : "r"(addr));
}
__device__ __forceinline__ void mma16816(float* c, unsigned int a0, unsigned int a1,
                                         unsigned int a2, unsigned int a3,
                                         unsigned int b0, unsigned int b1)
{
    asm volatile("mma.sync.aligned.m16n8k16.row.col.f32.f16.f16.f32 "
                 "{%0,%1,%2,%3}, {%4,%5,%6,%7}, {%8,%9}, {%0,%1,%2,%3};"
                 : "+f"(c[0]), "+f"(c[1]), "+f"(c[2]), "+f"(c[3])
                 : "r"(a0), "r"(a1), "r"(a2), "r"(a3), "r"(b0), "r"(b1));
}
__device__ __forceinline__ unsigned int packh2(float x, float y)
{
    __half2 h = __floats2half2_rn(x, y);
    return *reinterpret_cast<unsigned int*>(&h);
}
__device__ __forceinline__ float ex2f(float x)
{
    float r; asm("ex2.approx.ftz.f32 %0, %1;" : "=f"(r) : "f"(x)); return r;
}
__device__ __forceinline__ void cp16(unsigned int saddr, const void* gptr)
{
    asm volatile("cp.async.cg.shared.global [%0], [%1], 16;" :: "r"(saddr), "l"(gptr));
}
#define CP_COMMIT() asm volatile("cp.async.commit_group;")
#define CP_WAIT(n)  asm volatile("cp.async.wait_group %0;" :: "n"(n))

// ---------------------------------------------------------------------------
// Shared GEMM mainloop (split-fp16, fused fp32->hi/lo conversion, register-
// prefetch pipeline). CTA tile 128x64, BK=32, 8 warps (4m x 2n).
// Defined as a macro-free inline function writing to acc[2][4][4].
// ---------------------------------------------------------------------------
#define GS 40   // shared row stride in halfs (80B: conflict-free ldmatrix)

struct GemmSmem {
    __half sAh[128 * GS];
    __half sAl[128 * GS];
    __half sWh[64 * GS];
    __half sWl[64 * GS];
};

__device__ __forceinline__ void gemm_mainloop(const float* __restrict__ A,
                                              const float* __restrict__ W,
                                              GemmSmem* sm,
                                              int row0, int col0,
                                              int tid, int lane, int wm, int wn,
                                              float acc[2][4][4])
{
#pragma unroll
    for (int mt = 0; mt < 2; mt++)
#pragma unroll
        for (int n8 = 0; n8 < 4; n8++)
#pragma unroll
            for (int j = 0; j < 4; j++) acc[mt][n8][j] = 0.f;

    unsigned int ah_b = (unsigned int)__cvta_generic_to_shared(sm->sAh);
    unsigned int al_b = (unsigned int)__cvta_generic_to_shared(sm->sAl);
    unsigned int wh_b = (unsigned int)__cvta_generic_to_shared(sm->sWh);
    unsigned int wl_b = (unsigned int)__cvta_generic_to_shared(sm->sWl);

    int a_off = (wm * 32 + (lane & 15)) * GS + (lane >> 4) * 8;
    int w_off = (wn * 32 + (lane & 7) + ((lane >> 4) & 1) * 8) * GS + ((lane >> 3) & 1) * 8;

    float4 ra[4], rw[2];
#pragma unroll
    for (int p = 0; p < 4; p++) {
        int e = tid + p * 256;
        int r = e >> 3, c4 = (e & 7) * 4;
        ra[p] = *(const float4*)(A + (size_t)(row0 + r) * CC + c4);
    }
#pragma unroll
    for (int p = 0; p < 2; p++) {
        int e = tid + p * 256;
        int r = e >> 3, c4 = (e & 7) * 4;
        rw[p] = *(const float4*)(W + (size_t)(col0 + r) * CC + c4);
    }

    for (int k0 = 0; k0 < CC; k0 += 32) {
        __syncthreads();
#pragma unroll
        for (int p = 0; p < 4; p++) {
            int e = tid + p * 256;
            int r = e >> 3, c4 = (e & 7) * 4;
            float4 x = ra[p];
            __half2 h01 = __floats2half2_rn(x.x, x.y);
            __half2 h23 = __floats2half2_rn(x.z, x.w);
            float2 f01 = __half22float2(h01);
            float2 f23 = __half22float2(h23);
            __half2 l01 = __floats2half2_rn(x.x - f01.x, x.y - f01.y);
            __half2 l23 = __floats2half2_rn(x.z - f23.x, x.w - f23.y);
            uint2 ho, lo;
            ho.x = *reinterpret_cast<unsigned int*>(&h01);
            ho.y = *reinterpret_cast<unsigned int*>(&h23);
            lo.x = *reinterpret_cast<unsigned int*>(&l01);
            lo.y = *reinterpret_cast<unsigned int*>(&l23);
            *(uint2*)&sm->sAh[r * GS + c4] = ho;
            *(uint2*)&sm->sAl[r * GS + c4] = lo;
        }
#pragma unroll
        for (int p = 0; p < 2; p++) {
            int e = tid + p * 256;
            int r = e >> 3, c4 = (e & 7) * 4;
            float4 x = rw[p];
            __half2 h01 = __floats2half2_rn(x.x, x.y);
            __half2 h23 = __floats2half2_rn(x.z, x.w);
            float2 f01 = __half22float2(h01);
            float2 f23 = __half22float2(h23);
            __half2 l01 = __floats2half2_rn(x.x - f01.x, x.y - f01.y);
            __half2 l23 = __floats2half2_rn(x.z - f23.x, x.w - f23.y);
            uint2 ho, lo;
            ho.x = *reinterpret_cast<unsigned int*>(&h01);
            ho.y = *reinterpret_cast<unsigned int*>(&h23);
            lo.x = *reinterpret_cast<unsigned int*>(&l01);
            lo.y = *reinterpret_cast<unsigned int*>(&l23);
            *(uint2*)&sm->sWh[r * GS + c4] = ho;
            *(uint2*)&sm->sWl[r * GS + c4] = lo;
        }
        __syncthreads();

        if (k0 + 32 < CC) {
#pragma unroll
            for (int p = 0; p < 4; p++) {
                int e = tid + p * 256;
                int r = e >> 3, c4 = (e & 7) * 4;
                ra[p] = *(const float4*)(A + (size_t)(row0 + r) * CC + k0 + 32 + c4);
            }
#pragma unroll
            for (int p = 0; p < 2; p++) {
                int e = tid + p * 256;
                int r = e >> 3, c4 = (e & 7) * 4;
                rw[p] = *(const float4*)(W + (size_t)(col0 + r) * CC + k0 + 32 + c4);
            }
        }

#pragma unroll
        for (int kt = 0; kt < 2; kt++) {
            unsigned int ah[2][4], al[2][4];
#pragma unroll
            for (int mt = 0; mt < 2; mt++) {
                unsigned int off = (unsigned int)((a_off + mt * 16 * GS + kt * 16) * 2);
                ldsm_x4(ah_b + off, ah[mt][0], ah[mt][1], ah[mt][2], ah[mt][3]);
                ldsm_x4(al_b + off, al[mt][0], al[mt][1], al[mt][2], al[mt][3]);
            }
#pragma unroll
            for (int nt = 0; nt < 2; nt++) {
                unsigned int off = (unsigned int)((w_off + nt * 16 * GS + kt * 16) * 2);
                unsigned int wh0, wh1, wh2, wh3, wl0, wl1, wl2, wl3;
                ldsm_x4(wh_b + off, wh0, wh1, wh2, wh3);
                ldsm_x4(wl_b + off, wl0, wl1, wl2, wl3);
#pragma unroll
                for (int mt = 0; mt < 2; mt++) {
                    float* c0 = acc[mt][nt * 2 + 0];
                    float* c1 = acc[mt][nt * 2 + 1];
                    mma16816(c0, ah[mt][0], ah[mt][1], ah[mt][2], ah[mt][3], wh0, wh1);
                    mma16816(c1, ah[mt][0], ah[mt][1], ah[mt][2], ah[mt][3], wh2, wh3);
                    mma16816(c0, al[mt][0], al[mt][1], al[mt][2], al[mt][3], wh0, wh1);
                    mma16816(c1, al[mt][0], al[mt][1], al[mt][2], al[mt][3], wh2, wh3);
                    mma16816(c0, ah[mt][0], ah[mt][1], ah[mt][2], ah[mt][3], wl0, wl1);
                    mma16816(c1, ah[mt][0], ah[mt][1], ah[mt][2], ah[mt][3], wl2, wl3);
                }
            }
        }
    }
}

// ---------------------------------------------------------------------------
// QKV projection GEMM with FUSED RoPE + fp16 + head-major epilogue.
// blockIdx.z: 0 = Q (rope(qpos), *QMULT), 1 = K (rope(kpos)), 2 = V (plain).
// Accumulator col layout: c = col0 + wn*32 + n8*8 + (lane&3)*2 (+ j&1);
// the RoPE pair (c, c+8) is the (n8 even, n8 odd) pair — thread-local.
// ---------------------------------------------------------------------------
__global__ __launch_bounds__(256) void gemm_qkv(const float* __restrict__ A0,
                                                const float* __restrict__ A1,
                                                const float* __restrict__ A2,
                                                const float* __restrict__ W0,
                                                const float* __restrict__ W1,
                                                const float* __restrict__ W2,
                                                const float* __restrict__ b0,
                                                const float* __restrict__ b1,
                                                const float* __restrict__ b2,
                                                const int* __restrict__ qpos,
                                                const int* __restrict__ kpos,
                                                __half* __restrict__ Qh,
                                                __half* __restrict__ Kh,
                                                __half* __restrict__ Vh)
{
    int z = blockIdx.z;
    const float* A    = z == 0 ? A0 : (z == 1 ? A1 : A2);
    const float* W    = z == 0 ? W0 : (z == 1 ? W1 : W2);
    const float* bias = z == 0 ? b0 : (z == 1 ? b1 : b2);
    const int* pos    = z == 0 ? qpos : kpos;
    __half* dst       = z == 0 ? Qh : (z == 1 ? Kh : Vh);
    float mult        = z == 0 ? QMULT : 1.0f;

    __shared__ GemmSmem sm;
    int tid = threadIdx.x, lane = tid & 31, warp = tid >> 5;
    int wm = warp & 3, wn = warp >> 2;
    int row0 = blockIdx.y * 128;
    int col0 = blockIdx.x * 64;

    float acc[2][4][4];
    gemm_mainloop(A, W, &sm, row0, col0, tid, lane, wm, wn, acc);

    // Epilogue: bias + RoPE + fp16 + head-major store
    const float LOG2_100 = 6.643856189774724f;
    int jj0 = (lane & 3) * 2;
    float inv0 = exp2f(-(float)jj0 * 0.125f * LOG2_100);
    float inv1 = exp2f(-(float)(jj0 + 1) * 0.125f * LOG2_100);

#pragma unroll
    for (int mt = 0; mt < 2; mt++) {
        int t0 = row0 + wm * 32 + mt * 16 + (lane >> 2);
#pragma unroll
        for (int p = 0; p < 2; p++) {
            int c0 = col0 + wn * 32 + p * 16;    // 16-aligned chunk base
            int hh = c0 / HD;                    // head
            int chunk = c0 % HD;                 // 0, 16 or 32
            int a = chunk / 16;                  // spatial axis

            float bx1a = bias[c0 + jj0],     bx1b = bias[c0 + jj0 + 1];
            float bx2a = bias[c0 + 8 + jj0], bx2b = bias[c0 + 8 + jj0 + 1];

#pragma unroll
            for (int rh = 0; rh < 2; rh++) {     // row halves: t0, t0+8
                int t = t0 + rh * 8;
                float x1a = acc[mt][p * 2][rh * 2 + 0] + bx1a;
                float x1b = acc[mt][p * 2][rh * 2 + 1] + bx1b;
                float x2a = acc[mt][p * 2 + 1][rh * 2 + 0] + bx2a;
                float x2b = acc[mt][p * 2 + 1][rh * 2 + 1] + bx2b;

                if (z < 2) {
                    float pp = (float)pos[t * 3 + a];
                    float sa, ca, sb, cb;
                    sincosf(pp * inv0, &sa, &ca);
                    sincosf(pp * inv1, &sb, &cb);
                    float n1a = x1a * ca - x2a * sa;
                    float n2a = x2a * ca + x1a * sa;
                    float n1b = x1b * cb - x2b * sb;
                    float n2b = x2b * cb + x1b * sb;
                    x1a = n1a; x2a = n2a; x1b = n1b; x2b = n2b;
                }

                int bb = t / NN, nn = t % NN;
                __half* d = dst + ((size_t)(bb * HH + hh) * NN + nn) * HD + chunk + jj0;
                *(unsigned int*)d       = packh2(x1a * mult, x1b * mult);
                *(unsigned int*)(d + 8) = packh2(x2a * mult, x2b * mult);
            }
        }
    }
}

// ---------------------------------------------------------------------------
// Output projection GEMM (fp32 epilogue to d_out).
// ---------------------------------------------------------------------------
__global__ __launch_bounds__(256) void gemm_out(const float* __restrict__ A,
                                                const float* __restrict__ W,
                                                const float* __restrict__ bias,
                                                float* __restrict__ out)
{
    __shared__ GemmSmem sm;
    int tid = threadIdx.x, lane = tid & 31, warp = tid >> 5;
    int wm = warp & 3, wn = warp >> 2;
    int row0 = blockIdx.y * 128;
    int col0 = blockIdx.x * 64;

    float acc[2][4][4];
    gemm_mainloop(A, W, &sm, row0, col0, tid, lane, wm, wn, acc);

#pragma unroll
    for (int mt = 0; mt < 2; mt++) {
        int r = row0 + wm * 32 + mt * 16 + (lane >> 2);
#pragma unroll
        for (int n8 = 0; n8 < 4; n8++) {
            int c = col0 + wn * 32 + n8 * 8 + (lane & 3) * 2;
            float bx = bias[c], by = bias[c + 1];
            float2 f0, f1;
            f0.x = acc[mt][n8][0] + bx; f0.y = acc[mt][n8][1] + by;
            f1.x = acc[mt][n8][2] + bx; f1.y = acc[mt][n8][3] + by;
            *(float2*)&out[(size_t)r * CC + c] = f0;
            *(float2*)&out[(size_t)(r + 8) * CC + c] = f1;
        }
    }
}

// ---------------------------------------------------------------------------
// Tensor-core flash attention (validated R9/R10).
// ---------------------------------------------------------------------------
#define ATS 56
#define QT 128

__global__ __launch_bounds__(128) void attn_mma(const __half* __restrict__ Qh,
                                                const __half* __restrict__ Kh,
                                                const __half* __restrict__ Vh,
                                                float* __restrict__ X)
{
    __shared__ __half Qs[QT * ATS];
    __shared__ __half Ks[2][64 * ATS];
    __shared__ __half Vs[2][64 * ATS];

    int tid = threadIdx.x, lane = tid & 31, w = tid >> 5;
    int b = blockIdx.z, h = blockIdx.y;
    const size_t hb = ((size_t)(b * HH + h)) * NN * HD;
    int q0 = blockIdx.x * QT;

    unsigned int qs_base = (unsigned int)__cvta_generic_to_shared(Qs);
    unsigned int ks_base = (unsigned int)__cvta_generic_to_shared(&Ks[0][0]);
    unsigned int vs_base = (unsigned int)__cvta_generic_to_shared(&Vs[0][0]);
    const unsigned int BUFB = 64 * ATS * 2;

    for (int e = tid; e < QT * 6; e += 128) {
        int r = e / 6, c = e % 6;
        *(uint4*)&Qs[r * ATS + c * 8] = *(const uint4*)(Qh + hb + (size_t)(q0 + r) * HD + c * 8);
    }

    for (int e = tid; e < 384; e += 128) {
        int r = e / 6, c = e % 6;
        size_t g = hb + (size_t)r * HD + c * 8;
        unsigned int so = (unsigned int)((r * ATS + c * 8) * 2);
        cp16(ks_base + so, Kh + g);
        cp16(vs_base + so, Vh + g);
    }
    CP_COMMIT();
    __syncthreads();

    unsigned int qa[2][3][4];
#pragma unroll
    for (int mt = 0; mt < 2; mt++) {
        int arow = w * 32 + mt * 16 + (lane & 15);
        int acol = (lane >> 4) * 8;
#pragma unroll
        for (int k = 0; k < 3; k++) {
            unsigned int addr = qs_base + (unsigned int)((arow * ATS + k * 16 + acol) * 2);
            ldsm_x4(addr, qa[mt][k][0], qa[mt][k][1], qa[mt][k][2], qa[mt][k][3]);
        }
    }

    float o[2][6][4];
    float m[2][2], l[2][2];
#pragma unroll
    for (int mt = 0; mt < 2; mt++) {
        m[mt][0] = -1e30f; m[mt][1] = -1e30f;
        l[mt][0] = 0.f;    l[mt][1] = 0.f;
#pragma unroll
        for (int n = 0; n < 6; n++)
#pragma unroll
            for (int j = 0; j < 4; j++) o[mt][n][j] = 0.f;
    }

    int kb_off = ((lane & 7) + ((lane >> 4) & 1) * 8) * ATS + ((lane >> 3) & 1) * 8;
    int vb_off = ((lane & 7) + ((lane >> 3) & 1) * 8) * ATS + ((lane >> 4) & 1) * 8;

    const int NT = NN / 64;
    for (int kt = 0; kt < NT; kt++) {
        if (kt + 1 < NT) {
            unsigned int bo = ((kt + 1) & 1) * BUFB;
            for (int e = tid; e < 384; e += 128) {
                int r = e / 6, c = e % 6;
                size_t g = hb + (size_t)((kt + 1) * 64 + r) * HD + c * 8;
                unsigned int so = (unsigned int)((r * ATS + c * 8) * 2);
                cp16(ks_base + bo + so, Kh + g);
                cp16(vs_base + bo + so, Vh + g);
            }
            CP_COMMIT();
            CP_WAIT(1);
        } else {
            CP_WAIT(0);
        }
        __syncthreads();

        unsigned int bo = (kt & 1) * BUFB;

        float s[2][8][4];
#pragma unroll
        for (int mt = 0; mt < 2; mt++)
#pragma unroll
            for (int n = 0; n < 8; n++)
#pragma unroll
                for (int j = 0; j < 4; j++) s[mt][n][j] = 0.f;

#pragma unroll
        for (int np = 0; np < 4; np++) {
#pragma unroll
            for (int k = 0; k < 3; k++) {
                unsigned int addr = ks_base + bo +
                    (unsigned int)(((np * 16) * ATS + k * 16 + kb_off) * 2);
                unsigned int b0, b1, b2, b3;
                ldsm_x4(addr, b0, b1, b2, b3);
#pragma unroll
                for (int mt = 0; mt < 2; mt++) {
                    mma16816(s[mt][2 * np],     qa[mt][k][0], qa[mt][k][1], qa[mt][k][2], qa[mt][k][3], b0, b1);
                    mma16816(s[mt][2 * np + 1], qa[mt][k][0], qa[mt][k][1], qa[mt][k][2], qa[mt][k][3], b2, b3);
                }
            }
        }

        float tm[2][2];
#pragma unroll
        for (int mt = 0; mt < 2; mt++) {
            float t0 = s[mt][0][0], t1 = s[mt][0][2];
#pragma unroll
            for (int n = 0; n < 8; n++) {
                t0 = fmaxf(t0, fmaxf(s[mt][n][0], s[mt][n][1]));
                t1 = fmaxf(t1, fmaxf(s[mt][n][2], s[mt][n][3]));
            }
            t0 = fmaxf(t0, __shfl_xor_sync(0xffffffffu, t0, 1));
            t0 = fmaxf(t0, __shfl_xor_sync(0xffffffffu, t0, 2));
            t1 = fmaxf(t1, __shfl_xor_sync(0xffffffffu, t1, 1));
            t1 = fmaxf(t1, __shfl_xor_sync(0xffffffffu, t1, 2));
            tm[mt][0] = t0; tm[mt][1] = t1;
        }

        bool newmax = (tm[0][0] > m[0][0]) | (tm[0][1] > m[0][1]) |
                      (tm[1][0] > m[1][0]) | (tm[1][1] > m[1][1]);
        if (__any_sync(0xffffffffu, newmax)) {
#pragma unroll
            for (int mt = 0; mt < 2; mt++) {
                float nm0 = fmaxf(m[mt][0], tm[mt][0]);
                float nm1 = fmaxf(m[mt][1], tm[mt][1]);
                float al0 = ex2f(m[mt][0] - nm0);
                float al1 = ex2f(m[mt][1] - nm1);
                m[mt][0] = nm0; m[mt][1] = nm1;
                l[mt][0] *= al0; l[mt][1] *= al1;
#pragma unroll
                for (int n = 0; n < 6; n++) {
                    o[mt][n][0] *= al0; o[mt][n][1] *= al0;
                    o[mt][n][2] *= al1; o[mt][n][3] *= al1;
                }
            }
        }

#pragma unroll
        for (int mt = 0; mt < 2; mt++) {
            float l0 = 0.f, l1 = 0.f;
#pragma unroll
            for (int n = 0; n < 8; n++) {
                s[mt][n][0] = ex2f(s[mt][n][0] - m[mt][0]);
                s[mt][n][1] = ex2f(s[mt][n][1] - m[mt][0]);
                s[mt][n][2] = ex2f(s[mt][n][2] - m[mt][1]);
                s[mt][n][3] = ex2f(s[mt][n][3] - m[mt][1]);
                l0 += s[mt][n][0] + s[mt][n][1];
                l1 += s[mt][n][2] + s[mt][n][3];
            }
            l[mt][0] += l0; l[mt][1] += l1;
        }

#pragma unroll
        for (int k4 = 0; k4 < 4; k4++) {
            unsigned int a[2][4];
#pragma unroll
            for (int mt = 0; mt < 2; mt++) {
                a[mt][0] = packh2(s[mt][2 * k4][0],     s[mt][2 * k4][1]);
                a[mt][1] = packh2(s[mt][2 * k4][2],     s[mt][2 * k4][3]);
                a[mt][2] = packh2(s[mt][2 * k4 + 1][0], s[mt][2 * k4 + 1][1]);
                a[mt][3] = packh2(s[mt][2 * k4 + 1][2], s[mt][2 * k4 + 1][3]);
            }
#pragma unroll
            for (int np = 0; np < 3; np++) {
                unsigned int addr = vs_base + bo +
                    (unsigned int)(((k4 * 16) * ATS + np * 16 + vb_off) * 2);
                unsigned int b0, b1, b2, b3;
                ldsm_x4_t(addr, b0, b1, b2, b3);
#pragma unroll
                for (int mt = 0; mt < 2; mt++) {
                    mma16816(o[mt][2 * np],     a[mt][0], a[mt][1], a[mt][2], a[mt][3], b0, b1);
                    mma16816(o[mt][2 * np + 1], a[mt][0], a[mt][1], a[mt][2], a[mt][3], b2, b3);
                }
            }
        }
        __syncthreads();
    }

#pragma unroll
    for (int mt = 0; mt < 2; mt++) {
        float l0 = l[mt][0], l1 = l[mt][1];
        l0 += __shfl_xor_sync(0xffffffffu, l0, 1);
        l0 += __shfl_xor_sync(0xffffffffu, l0, 2);
        l1 += __shfl_xor_sync(0xffffffffu, l1, 1);
        l1 += __shfl_xor_sync(0xffffffffu, l1, 2);
        float i0 = 1.f / l0, i1 = 1.f / l1;

        int r0 = q0 + w * 32 + mt * 16 + (lane >> 2);
        int cbase = h * HD + (lane & 3) * 2;
#pragma unroll
        for (int n = 0; n < 6; n++) {
            float2 f0; f0.x = o[mt][n][0] * i0; f0.y = o[mt][n][1] * i0;
            float2 f1; f1.x = o[mt][n][2] * i1; f1.y = o[mt][n][3] * i1;
            *(float2*)&X[(size_t)(b * NN + r0) * CC + cbase + n * 8] = f0;
            *(float2*)&X[(size_t)(b * NN + r0 + 8) * CC + cbase + n * 8] = f1;
        }
    }
}

// ---------------------------------------------------------------------------
// Launch
// ---------------------------------------------------------------------------
extern "C" void kernel_launch(void* const* d_in, const int* in_sizes, int n_in,
                              void* d_out, int out_size)
{
    const float* query = (const float*)d_in[0];
    const float* key   = (const float*)d_in[1];
    const float* value = (const float*)d_in[2];
    const float* Wq = (const float*)d_in[3];
    const float* bq = (const float*)d_in[4];
    const float* Wk = (const float*)d_in[5];
    const float* bk = (const float*)d_in[6];
    const float* Wv = (const float*)d_in[7];
    const float* bv = (const float*)d_in[8];
    const float* Wo = (const float*)d_in[9];
    const float* bo = (const float*)d_in[10];
    const int* qpos = (const int*)d_in[11];
    const int* kpos = (const int*)d_in[12];
    float* out = (float*)d_out;

    float* pX;
    __half *pQh, *pKh, *pVh;
    cudaGetSymbolAddress((void**)&pX, g_X);
    cudaGetSymbolAddress((void**)&pQh, g_Qh);
    cudaGetSymbolAddress((void**)&pKh, g_Kh);
    cudaGetSymbolAddress((void**)&pVh, g_Vh);

    // Q/K/V projections + RoPE + fp16 head-major, ONE launch
    dim3 g3(CC / 64, TT / 128, 3);   // (6, 64, 3) = 1152 CTAs
    gemm_qkv<<<g3, 256>>>(query, key, value,
                          Wq, Wk, Wv,
                          bq, bk, bv,
                          qpos, kpos,
                          pQh, pKh, pVh);

    attn_mma<<<dim3(NN / QT, HH, BB), 128>>>(pQh, pKh, pVh, pX);

    dim3 g1(CC / 64, TT / 128);
    gemm_out<<<g1, 256>>>(pX, Wo, bo, out);
}